// round 8
// baseline (speedup 1.0000x reference)
#include <cuda_runtime.h>
#include <cuda_bf16.h>
#include <math.h>
#include <stdint.h>

#define NN 1000
#define FF 64
#define SS 192          // B*T snapshots
#define EE 16000
#define CC 10
#define BBATCH 16
#define JTOT 768000     // T*N*F
#define LN_EPS 1e-5f
#define FCHUNKS 192
#define CHUNK_J 4000

// ---------------- scratch (static device globals; no allocation) -------------
__device__ float g_basis[8][SS * NN * FF];             // fp32 planes (recurrence state)
__device__ float g_h[SS * NN * FF];
__device__ __nv_bfloat16 g_Abf[9][SS][8][2][8192];     // [slot][s][tile][hi/lo][swizzled 128m x 64k]
__device__ __nv_bfloat16 g_Bpack[2][9][8192];          // [hi/lo][slot][swizzled 128n x 64k]
__device__ float g_bcat[128];
__device__ int   g_deg_out[NN], g_deg_in[NN];
__device__ int   g_offA[NN + 1], g_offB[NN + 1];
__device__ int   g_adjA_src[EE];
__device__ float g_adjA_w[EE];
__device__ int   g_adjB_src[EE];
__device__ float g_inv_deg_in[NN];
__device__ float g_partial[FCHUNKS * BBATCH * CC];

// ---------------- helpers -----------------------------------------------------
__device__ __forceinline__ uint32_t smem_u32(const void* p) {
    uint32_t a;
    asm("{ .reg .u64 t; cvta.to.shared.u64 t, %1; cvt.u32.u64 %0, t; }" : "=r"(a) : "l"(p));
    return a;
}
#define SWZ128(o) ((o) ^ (((o) >> 3) & 0x70))

__device__ __forceinline__ void cpa16(uint32_t dst, const void* src) {
    asm volatile("cp.async.cg.shared.global [%0], [%1], 16;" :: "r"(dst), "l"(src));
}

__device__ __forceinline__ void ldsm4(uint32_t* r, uint32_t addr) {
    asm volatile("ldmatrix.sync.aligned.m8n8.x4.shared.b16 {%0,%1,%2,%3}, [%4];"
        : "=r"(r[0]), "=r"(r[1]), "=r"(r[2]), "=r"(r[3]) : "r"(addr));
}

__device__ __forceinline__ void mma_bf16(float* d, const uint32_t* a, const uint32_t* b) {
    asm volatile(
        "mma.sync.aligned.m16n8k16.row.col.f32.bf16.bf16.f32 "
        "{%0,%1,%2,%3}, {%4,%5,%6,%7}, {%8,%9}, {%0,%1,%2,%3};"
        : "+f"(d[0]), "+f"(d[1]), "+f"(d[2]), "+f"(d[3])
        : "r"(a[0]), "r"(a[1]), "r"(a[2]), "r"(a[3]), "r"(b[0]), "r"(b[1]));
}

// ---------------- graph preprocessing ----------------------------------------
__global__ void k_zero_deg() {
    int i = blockIdx.x * blockDim.x + threadIdx.x;
    if (i < NN) { g_deg_out[i] = 0; g_deg_in[i] = 0; }
}

__global__ void k_count(const int* __restrict__ ei) {
    int e = blockIdx.x * blockDim.x + threadIdx.x;
    if (e < EE) {
        atomicAdd(&g_deg_out[ei[e]], 1);
        atomicAdd(&g_deg_in[ei[EE + e]], 1);
    }
}

// parallel exclusive scan, single block of 1024
__global__ void k_scan() {
    __shared__ int sA[1024], sB[1024];
    int i = threadIdx.x;
    int da = (i < NN) ? g_deg_in[i] : 0;
    int db = (i < NN) ? g_deg_out[i] : 0;
    sA[i] = da; sB[i] = db;
    __syncthreads();
    for (int off = 1; off < 1024; off <<= 1) {
        int va = (i >= off) ? sA[i - off] : 0;
        int vb = (i >= off) ? sB[i - off] : 0;
        __syncthreads();
        sA[i] += va; sB[i] += vb;
        __syncthreads();
    }
    if (i < NN) {
        g_offA[i] = sA[i] - da;
        g_offB[i] = sB[i] - db;
        g_inv_deg_in[i] = 1.0f / (float)da;
    }
    if (i == 0) { g_offA[NN] = sA[NN - 1]; g_offB[NN] = sB[NN - 1]; }
}

// deterministic CSR build: stage all edges in smem, one warp per node, ballot compaction
__global__ void k_build(const int* __restrict__ ei) {
    extern __shared__ int2 se[];                   // 16000 x 8B = 128KB
    int tid = threadIdx.x;
    for (int i = tid; i < EE; i += blockDim.x)
        se[i] = make_int2(ei[i], ei[EE + i]);
    __syncthreads();
    int warp = blockIdx.x * (blockDim.x >> 5) + (tid >> 5);
    int lane = tid & 31;
    if (warp >= NN) return;
    int n = warp;
    int pa = g_offA[n], pb = g_offB[n];
    for (int e0 = 0; e0 < EE; e0 += 32) {
        int2 rc = se[e0 + lane];
        unsigned mA = __ballot_sync(0xffffffffu, rc.y == n);
        unsigned mB = __ballot_sync(0xffffffffu, rc.x == n);
        if (rc.y == n) {
            int pos = pa + __popc(mA & ((1u << lane) - 1));
            g_adjA_src[pos] = rc.x;
            g_adjA_w[pos] = 1.0f / (float)g_deg_out[rc.x];
        }
        if (rc.x == n) {
            int pos = pb + __popc(mB & ((1u << lane) - 1));
            g_adjB_src[pos] = rc.y;
        }
        pa += __popc(mA); pb += __popc(mB);
    }
}

// pack weights into bf16 hi/lo images (SW128-swizzled, [n][k] rows of 128B)
__global__ void k_packW(const float* __restrict__ Wz, const float* __restrict__ bz,
                        const float* __restrict__ Wh, const float* __restrict__ bh) {
    int i = blockIdx.x * blockDim.x + threadIdx.x;
    if (i < 128) g_bcat[i] = (i < 64) ? bz[i] : bh[i - 64];
    if (i >= 9 * 8192) return;
    int slot = i >> 13;
    int r = i & 8191;
    int n = r >> 6, k = r & 63;
    const float* W = (n < 64) ? Wz : Wh;
    int f = n & 63;
    float v;
    if (slot == 0) {
        v = W[(0 * 5 + 0) * 128 * 64 + k * 64 + f]
          + W[(1 * 5 + 0) * 128 * 64 + k * 64 + f];
    } else {
        int kc = (slot + 1) >> 1;
        int dir = (slot - 1) & 1;
        v = W[(dir * 5 + kc) * 128 * 64 + k * 64 + f];
    }
    __nv_bfloat16 hi = __float2bfloat16(v);
    __nv_bfloat16 lo = __float2bfloat16(v - __bfloat162float(hi));
    uint32_t off = SWZ128((uint32_t)(n * 128 + k * 2));
    g_Bpack[0][slot][off >> 1] = hi;
    g_Bpack[1][slot][off >> 1] = lo;
}

// convert x into slot-0 bf16 hi/lo tile images; zero tile-7 pad rows for all slots
__global__ void k_convx(const float* __restrict__ x) {
    int s = blockIdx.x, t = blockIdx.y;
    int tid = threadIdx.x;
    char* imgH = (char*)&g_Abf[0][s][t][0][0];
    char* imgL = (char*)&g_Abf[0][s][t][1][0];
    #pragma unroll
    for (int i = 0; i < 8; i++) {
        int j = tid + i * 256;
        int row = j >> 4, kq = j & 15;
        int node = t * 128 + row;
        float4 v = (node < NN) ? *(const float4*)(x + ((size_t)s * NN + node) * FF + kq * 4)
                               : make_float4(0.f, 0.f, 0.f, 0.f);
        __nv_bfloat16 h0 = __float2bfloat16(v.x);
        __nv_bfloat16 h1 = __float2bfloat16(v.y);
        __nv_bfloat16 h2 = __float2bfloat16(v.z);
        __nv_bfloat16 h3 = __float2bfloat16(v.w);
        __nv_bfloat16 l0 = __float2bfloat16(v.x - __bfloat162float(h0));
        __nv_bfloat16 l1 = __float2bfloat16(v.y - __bfloat162float(h1));
        __nv_bfloat16 l2 = __float2bfloat16(v.z - __bfloat162float(h2));
        __nv_bfloat16 l3 = __float2bfloat16(v.w - __bfloat162float(h3));
        uint32_t off = SWZ128((uint32_t)(row * 128 + kq * 8));
        *(__nv_bfloat162*)(imgH + off)     = __halves2bfloat162(h0, h1);
        *(__nv_bfloat162*)(imgH + off + 4) = __halves2bfloat162(h2, h3);
        *(__nv_bfloat162*)(imgL + off)     = __halves2bfloat162(l0, l1);
        *(__nv_bfloat162*)(imgL + off + 4) = __halves2bfloat162(l2, l3);
    }
    // zero pad rows (104..127) of tile 7 for slots 1..8 (prop only writes valid nodes)
    if (t == 7) {
        for (int i = tid; i < 8 * 2 * 192; i += 256) {
            int slot = (i / 384) + 1;
            int rest = i % 384;
            int img = rest / 192, u = rest % 192;
            *(uint4*)((char*)&g_Abf[slot][s][7][img][0] + 104 * 128 + u * 16) =
                make_uint4(0u, 0u, 0u, 0u);
        }
    }
}

// ---------------- Chebyshev propagation (smem-cached gather) ------------------
// Writes fp32 plane (recurrence state, levels 1-3 only) AND bf16 hi/lo tile image.
__global__ void k_prop(const float* __restrict__ x, int level) {
    extern __shared__ float sm[];
    int s = blockIdx.x, dir = blockIdx.y, half = blockIdx.z;
    int dst_slot = 2 * level - 1 + dir;
    const float* src;
    const float* prev = nullptr;
    if (level == 1) {
        src = x + (size_t)s * NN * FF;
    } else {
        int ssrc = 2 * (level - 1) - 1 + dir;
        src = g_basis[ssrc - 1] + (size_t)s * NN * FF;
        if (level == 2) prev = x + (size_t)s * NN * FF;
        else prev = g_basis[(2 * (level - 2) - 1) - 1] + (size_t)s * NN * FF;
    }
    for (int i = threadIdx.x; i < NN * 32; i += blockDim.x) {
        int n = i >> 5, f = i & 31;
        sm[i] = src[n * FF + half * 32 + f];
    }
    __syncthreads();

    int lane = threadIdx.x & 31;
    int w = threadIdx.x >> 5;
    int nw = blockDim.x >> 5;
    float* out = g_basis[dst_slot - 1] + (size_t)s * NN * FF;

    for (int n = w; n < NN; n += nw) {
        float acc = 0.0f;
        if (dir == 0) {
            int b = g_offA[n], e = g_offA[n + 1];
            #pragma unroll 4
            for (int j = b; j < e; j++)
                acc += sm[g_adjA_src[j] * 32 + lane] * g_adjA_w[j];
        } else {
            int b = g_offB[n], e = g_offB[n + 1];
            #pragma unroll 4
            for (int j = b; j < e; j++)
                acc += sm[g_adjB_src[j] * 32 + lane];
            acc *= g_inv_deg_in[n];
        }
        int f = half * 32 + lane;
        float r = (level == 1) ? acc : 2.0f * acc - prev[n * FF + f];
        if (level < 4) out[n * FF + f] = r;               // slots 7,8 never re-read as fp32
        // bf16 hi/lo split into the GEMM tile image
        int t = n >> 7, row = n & 127;
        uint32_t off = SWZ128((uint32_t)(row * 128 + f * 2));
        __nv_bfloat16 hi = __float2bfloat16(r);
        __nv_bfloat16 lo = __float2bfloat16(r - __bfloat162float(hi));
        *(__nv_bfloat16*)((char*)&g_Abf[dst_slot][s][t][0][0] + off) = hi;
        *(__nv_bfloat16*)((char*)&g_Abf[dst_slot][s][t][1][0] + off) = lo;
    }
}

// ---------------- pipelined mma.sync bf16 GEMM + fused gate/LN epilogue -------
// Block: 256 thr = 8 warps; one (snapshot, 128-row tile). Warp w: rows w*16..+16,
// all 128 cols. 3-pass bf16 split, fp32 accum. cp.async double-buffered slots.
#define STG 65536       // stage stride: [Ahi 16K][Alo 16K][Bhi 16K][Blo 16K]
#define SM_TOTAL_GEMM (2 * STG)

__global__ void __launch_bounds__(256, 1) k_gemm_mma(const float* __restrict__ ln_g,
                                                     const float* __restrict__ ln_b) {
    extern __shared__ char smem[];
    uint32_t sb = smem_u32(smem);
    const int tid = threadIdx.x;
    const int wid = tid >> 5, lane = tid & 31;
    const int s = blockIdx.x >> 3;
    const int tile = blockIdx.x & 7;
    const int row0 = tile << 7;
    const int m0 = wid << 4;

    float acc[16][4];
    #pragma unroll
    for (int t = 0; t < 16; t++)
        #pragma unroll
        for (int c = 0; c < 4; c++) acc[t][c] = 0.0f;

    const uint32_t a_rowoff = (uint32_t)((m0 + (lane & 15)) * 128 + ((lane >> 4) * 16));
    const uint32_t b_rowoff = (uint32_t)((((lane >> 4) * 8 + (lane & 7)) * 128) + (((lane >> 3) & 1) * 16));

    auto issue = [&](int slot, int stage) {
        const char* srcs[4] = {
            (const char*)&g_Abf[slot][s][tile][0][0],
            (const char*)&g_Abf[slot][s][tile][1][0],
            (const char*)&g_Bpack[0][slot][0],
            (const char*)&g_Bpack[1][slot][0] };
        #pragma unroll
        for (int rgn = 0; rgn < 4; rgn++) {
            uint32_t dbase = sb + stage * STG + rgn * 16384;
            #pragma unroll
            for (int i = 0; i < 4; i++) {
                int idx = tid + i * 256;
                cpa16(dbase + idx * 16, srcs[rgn] + idx * 16);
            }
        }
        asm volatile("cp.async.commit_group;" ::: "memory");
    };

    issue(0, 0);
    for (int slot = 0; slot < 9; slot++) {
        int stage = slot & 1;
        if (slot < 8) {
            issue(slot + 1, stage ^ 1);
            asm volatile("cp.async.wait_group 1;" ::: "memory");
        } else {
            asm volatile("cp.async.wait_group 0;" ::: "memory");
        }
        __syncthreads();
        uint32_t bAH = sb + stage * STG;
        uint32_t bAL = bAH + 16384;
        uint32_t bBH = bAH + 32768;
        uint32_t bBL = bAH + 49152;
        #pragma unroll
        for (int kk = 0; kk < 4; kk++) {
            const uint32_t kbase = kk * 32;
            uint32_t aAh[4], aAl[4];
            ldsm4(aAh, bAH + SWZ128(a_rowoff + kbase));
            ldsm4(aAl, bAL + SWZ128(a_rowoff + kbase));
            uint32_t bF[8][4];
            #pragma unroll
            for (int p = 0; p < 8; p++)
                ldsm4(bF[p], bBH + SWZ128(b_rowoff + p * 2048 + kbase));
            #pragma unroll
            for (int t = 0; t < 16; t++) {
                const uint32_t* bf = &bF[t >> 1][(t & 1) * 2];
                mma_bf16(acc[t], aAh, bf);     // Ahi * Bhi
                mma_bf16(acc[t], aAl, bf);     // Alo * Bhi
            }
            #pragma unroll
            for (int p = 0; p < 8; p++)
                ldsm4(bF[p], bBL + SWZ128(b_rowoff + p * 2048 + kbase));
            #pragma unroll
            for (int t = 0; t < 16; t++)
                mma_bf16(acc[t], aAh, &bF[t >> 1][(t & 1) * 2]);   // Ahi * Blo
        }
        __syncthreads();
    }

    // fused epilogue: gates + relu + LayerNorm, register/shfl local
    int q = lane & 3, rl = lane >> 2;
    #pragma unroll
    for (int h = 0; h < 2; h++) {
        float s1 = 0.f, s2 = 0.f;
        float vals[16];
        #pragma unroll
        for (int j = 0; j < 8; j++) {
            #pragma unroll
            for (int p = 0; p < 2; p++) {
                int col = j * 8 + q * 2 + p;
                float zc = acc[j][h * 2 + p] + g_bcat[col];
                float tc = acc[8 + j][h * 2 + p] + g_bcat[64 + col];
                float z = 1.0f / (1.0f + expf(-zc));
                float tt = tanhf(tc);
                float v = fmaxf((1.0f - z) * tt, 0.0f);
                vals[j * 2 + p] = v; s1 += v; s2 += v * v;
            }
        }
        s1 += __shfl_xor_sync(0xffffffffu, s1, 1);
        s1 += __shfl_xor_sync(0xffffffffu, s1, 2);
        s2 += __shfl_xor_sync(0xffffffffu, s2, 1);
        s2 += __shfl_xor_sync(0xffffffffu, s2, 2);
        float mu = s1 * (1.0f / 64.0f);
        float var = s2 * (1.0f / 64.0f) - mu * mu;
        float rstd = rsqrtf(var + LN_EPS);
        int node = row0 + m0 + rl + h * 8;
        if (node < NN) {
            float* o = g_h + ((size_t)s * NN + node) * FF;
            #pragma unroll
            for (int j = 0; j < 8; j++) {
                int col = j * 8 + q * 2;
                float2 w;
                w.x = (vals[j * 2 + 0] - mu) * rstd * ln_g[col] + ln_b[col];
                w.y = (vals[j * 2 + 1] - mu) * rstd * ln_g[col + 1] + ln_b[col + 1];
                *(float2*)(o + col) = w;
            }
        }
    }
}

// ---------------- final thin GEMM [16,768000] x [768000,10] -------------------
__global__ void __launch_bounds__(256) k_final1(const float* __restrict__ lin_w) {
    int chunk = blockIdx.x;
    int j0 = chunk * CHUNK_J;
    int tid = threadIdx.x;
    int bg = tid >> 6;
    int kl = tid & 63;
    float acc[4][10];
    #pragma unroll
    for (int bi = 0; bi < 4; bi++)
        #pragma unroll
        for (int c = 0; c < 10; c++) acc[bi][c] = 0.0f;

    for (int k = j0 + kl; k < j0 + CHUNK_J; k += 64) {
        float w[10];
        #pragma unroll
        for (int c = 0; c < 10; c++) w[c] = lin_w[(size_t)c * JTOT + k];
        #pragma unroll
        for (int bi = 0; bi < 4; bi++) {
            float h = g_h[(size_t)(bg * 4 + bi) * JTOT + k];
            #pragma unroll
            for (int c = 0; c < 10; c++) acc[bi][c] += h * w[c];
        }
    }
    __shared__ float red[256 * 40];
    #pragma unroll
    for (int bi = 0; bi < 4; bi++)
        #pragma unroll
        for (int c = 0; c < 10; c++) red[tid * 40 + bi * 10 + c] = acc[bi][c];
    __syncthreads();
    if (tid < 160) {
        int b = tid / 10, c = tid % 10;
        int bg2 = b >> 2, bi2 = b & 3;
        float sum = 0.0f;
        for (int l = 0; l < 64; l++)
            sum += red[(bg2 * 64 + l) * 40 + bi2 * 10 + c];
        g_partial[(chunk * BBATCH + b) * CC + c] = sum;
    }
}

__global__ void k_final2(const float* __restrict__ lin_b, float* __restrict__ out) {
    int i = threadIdx.x;
    if (i < BBATCH * CC) {
        int b = i / CC, c = i % CC;
        float s = lin_b[c];
        for (int ch = 0; ch < FCHUNKS; ch++)
            s += g_partial[(ch * BBATCH + b) * CC + c];
        out[b * CC + c] = s;
    }
}

// ---------------- launch ------------------------------------------------------
extern "C" void kernel_launch(void* const* d_in, const int* in_sizes, int n_in,
                              void* d_out, int out_size) {
    const float* x   = (const float*)d_in[0];
    const int*   ei  = (const int*)d_in[1];
    const float* Wz  = (const float*)d_in[2];
    const float* bz  = (const float*)d_in[3];
    // d_in[4]=W_r, d_in[5]=b_r provably unused (h0 == 0)
    const float* Wh  = (const float*)d_in[6];
    const float* bh  = (const float*)d_in[7];
    const float* lng = (const float*)d_in[8];
    const float* lnb = (const float*)d_in[9];
    const float* lw  = (const float*)d_in[10];
    const float* lb  = (const float*)d_in[11];
    float* out = (float*)d_out;

    cudaFuncSetAttribute(k_prop, cudaFuncAttributeMaxDynamicSharedMemorySize, 131072);
    cudaFuncSetAttribute(k_build, cudaFuncAttributeMaxDynamicSharedMemorySize, EE * 8);
    cudaFuncSetAttribute(k_gemm_mma, cudaFuncAttributeMaxDynamicSharedMemorySize, SM_TOTAL_GEMM);

    k_zero_deg<<<1, 1024>>>();
    k_count<<<(EE + 255) / 256, 256>>>(ei);
    k_scan<<<1, 1024>>>();
    k_build<<<(NN + 7) / 8, 256, EE * 8>>>(ei);
    k_packW<<<(9 * 8192 + 255) / 256, 256>>>(Wz, bz, Wh, bh);
    k_convx<<<dim3(SS, 8), 256>>>(x);

    for (int lvl = 1; lvl <= 4; lvl++)
        k_prop<<<dim3(SS, 2, 2), 512, NN * 32 * sizeof(float)>>>(x, lvl);

    k_gemm_mma<<<SS * 8, 256, SM_TOTAL_GEMM>>>(lng, lnb);
    k_final1<<<FCHUNKS, 256>>>(lw);
    k_final2<<<1, 192>>>(lb, out);
}

// round 10
// speedup vs baseline: 1.2067x; 1.2067x over previous
#include <cuda_runtime.h>
#include <cuda_bf16.h>
#include <math.h>
#include <stdint.h>

#define NN 1000
#define FF 64
#define SS 192          // B*T snapshots
#define EE 16000
#define CC 10
#define BBATCH 16
#define JTOT 768000     // T*N*F
#define LN_EPS 1e-5f
#define FCHUNKS 192
#define CHUNK_J 4000

// ---------------- scratch (static device globals; no allocation) -------------
__device__ float g_basis[8][SS * NN * FF];
__device__ float g_h[SS * NN * FF];
__device__ __nv_bfloat16 g_Bpack[2][9][8192];   // [hi/lo][slot][swizzled 128n x 64k]
__device__ float g_bcat[128];
__device__ int   g_deg_out[NN], g_deg_in[NN];
__device__ int   g_offA[NN + 8], g_offB[NN + 8];   // padded for 16B cp.async reads
__device__ int2  g_adjA2[EE];                    // prop_out: (src, bits(1/deg_out[src]))
__device__ int   g_adjB_src[EE];                 // prop_in : grouped by row, src=col
__device__ float g_inv_deg_in[NN];
__device__ float g_partial[FCHUNKS * BBATCH * CC];

// ---------------- helpers -----------------------------------------------------
__device__ __forceinline__ uint32_t smem_u32(const void* p) {
    uint32_t a;
    asm("{ .reg .u64 t; cvta.to.shared.u64 t, %1; cvt.u32.u64 %0, t; }" : "=r"(a) : "l"(p));
    return a;
}
#define SWZ128(o) ((o) ^ (((o) >> 3) & 0x70))

__device__ __forceinline__ void cpa16(uint32_t dst, const void* src) {
    asm volatile("cp.async.cg.shared.global [%0], [%1], 16;" :: "r"(dst), "l"(src));
}
__device__ __forceinline__ void cpa_commit_wait() {
    asm volatile("cp.async.commit_group;" ::: "memory");
    asm volatile("cp.async.wait_group 0;" ::: "memory");
}

__device__ __forceinline__ void ldsm4(uint32_t* r, uint32_t addr) {
    asm volatile("ldmatrix.sync.aligned.m8n8.x4.shared.b16 {%0,%1,%2,%3}, [%4];"
        : "=r"(r[0]), "=r"(r[1]), "=r"(r[2]), "=r"(r[3]) : "r"(addr));
}

__device__ __forceinline__ void mma_bf16(float* d, const uint32_t* a, const uint32_t* b) {
    asm volatile(
        "mma.sync.aligned.m16n8k16.row.col.f32.bf16.bf16.f32 "
        "{%0,%1,%2,%3}, {%4,%5,%6,%7}, {%8,%9}, {%0,%1,%2,%3};"
        : "+f"(d[0]), "+f"(d[1]), "+f"(d[2]), "+f"(d[3])
        : "r"(a[0]), "r"(a[1]), "r"(a[2]), "r"(a[3]), "r"(b[0]), "r"(b[1]));
}

// ---------------- graph preprocessing ----------------------------------------
__global__ void k_zero_deg() {
    int i = blockIdx.x * blockDim.x + threadIdx.x;
    if (i < NN) { g_deg_out[i] = 0; g_deg_in[i] = 0; }
}

__global__ void k_count(const int* __restrict__ ei) {
    int e = blockIdx.x * blockDim.x + threadIdx.x;
    if (e < EE) {
        atomicAdd(&g_deg_out[ei[e]], 1);
        atomicAdd(&g_deg_in[ei[EE + e]], 1);
    }
}

// parallel exclusive scan, single block of 1024
__global__ void k_scan() {
    __shared__ int sA[1024], sB[1024];
    int i = threadIdx.x;
    int da = (i < NN) ? g_deg_in[i] : 0;
    int db = (i < NN) ? g_deg_out[i] : 0;
    sA[i] = da; sB[i] = db;
    __syncthreads();
    for (int off = 1; off < 1024; off <<= 1) {
        int va = (i >= off) ? sA[i - off] : 0;
        int vb = (i >= off) ? sB[i - off] : 0;
        __syncthreads();
        sA[i] += va; sB[i] += vb;
        __syncthreads();
    }
    if (i < NN) {
        g_offA[i] = sA[i] - da;
        g_offB[i] = sB[i] - db;
        g_inv_deg_in[i] = 1.0f / (float)da;
    }
    if (i == 0) { g_offA[NN] = sA[NN - 1]; g_offB[NN] = sB[NN - 1]; }
}

// deterministic CSR build: stage all edges in smem, one warp per node, ballot compaction
__global__ void k_build(const int* __restrict__ ei) {
    extern __shared__ int2 se[];                   // 16000 x 8B = 128KB
    int tid = threadIdx.x;
    for (int i = tid; i < EE; i += blockDim.x)
        se[i] = make_int2(ei[i], ei[EE + i]);
    __syncthreads();
    int warp = blockIdx.x * (blockDim.x >> 5) + (tid >> 5);
    int lane = tid & 31;
    if (warp >= NN) return;
    int n = warp;
    int pa = g_offA[n], pb = g_offB[n];
    for (int e0 = 0; e0 < EE; e0 += 32) {
        int2 rc = se[e0 + lane];
        unsigned mA = __ballot_sync(0xffffffffu, rc.y == n);
        unsigned mB = __ballot_sync(0xffffffffu, rc.x == n);
        if (rc.y == n) {
            int pos = pa + __popc(mA & ((1u << lane) - 1));
            g_adjA2[pos] = make_int2(rc.x, __float_as_int(1.0f / (float)g_deg_out[rc.x]));
        }
        if (rc.x == n) {
            int pos = pb + __popc(mB & ((1u << lane) - 1));
            g_adjB_src[pos] = rc.y;
        }
        pa += __popc(mA); pb += __popc(mB);
    }
}

// pack weights into bf16 hi/lo images (SW128-swizzled, [n][k] rows of 128B)
__global__ void k_packW(const float* __restrict__ Wz, const float* __restrict__ bz,
                        const float* __restrict__ Wh, const float* __restrict__ bh) {
    int i = blockIdx.x * blockDim.x + threadIdx.x;
    if (i < 128) g_bcat[i] = (i < 64) ? bz[i] : bh[i - 64];
    if (i >= 9 * 8192) return;
    int slot = i >> 13;
    int r = i & 8191;
    int n = r >> 6, k = r & 63;
    const float* W = (n < 64) ? Wz : Wh;
    int f = n & 63;
    float v;
    if (slot == 0) {
        v = W[(0 * 5 + 0) * 128 * 64 + k * 64 + f]
          + W[(1 * 5 + 0) * 128 * 64 + k * 64 + f];
    } else {
        int kc = (slot + 1) >> 1;
        int dir = (slot - 1) & 1;
        v = W[(dir * 5 + kc) * 128 * 64 + k * 64 + f];
    }
    __nv_bfloat16 hi = __float2bfloat16(v);
    __nv_bfloat16 lo = __float2bfloat16(v - __bfloat162float(hi));
    uint32_t off = SWZ128((uint32_t)(n * 128 + k * 2));
    g_Bpack[0][slot][off >> 1] = hi;
    g_Bpack[1][slot][off >> 1] = lo;
}

// ---------------- Chebyshev propagation (optimized gather) --------------------
// cp.async smem fill; CSR offsets in smem; int2-packed adjacency; unrolled
// multi-accumulator edge loops. Recurrence: both dirs subtract OUT-dir prev.
#define PROP_SMEM (32000 * 4 + 1008 * 4)

__global__ void __launch_bounds__(512, 1) a_prop(const float* __restrict__ x, int level) {
    extern __shared__ float sv[];                  // [32000] values
    int* soff = (int*)(sv + 32000);                // [1008] CSR offsets (this dir)
    int s = blockIdx.x, dir = blockIdx.y, half = blockIdx.z;
    int dst_slot = 2 * level - 1 + dir;
    const float* src;
    const float* prev = nullptr;
    if (level == 1) {
        src = x + (size_t)s * NN * FF;
    } else {
        int ssrc = 2 * (level - 1) - 1 + dir;
        src = g_basis[ssrc - 1] + (size_t)s * NN * FF;
        if (level == 2) prev = x + (size_t)s * NN * FF;
        else prev = g_basis[(2 * (level - 2) - 1) - 1] + (size_t)s * NN * FF;
    }
    uint32_t sb = smem_u32(sv);
    int tid = threadIdx.x;
    // fill values: 8000 x 16B chunks; chunk i: node n=i>>3, quad q=i&7
    #pragma unroll
    for (int it = 0; it < 16; it++) {
        int i = tid + it * 512;
        if (i < 8000) {
            int n = i >> 3, q = i & 7;
            cpa16(sb + (uint32_t)(n * 128 + q * 16),
                  src + (size_t)n * FF + half * 32 + q * 4);
        }
    }
    // fill offsets: 1004 ints = 251 chunks
    {
        const int* offsrc = dir ? g_offB : g_offA;
        if (tid < 251)
            cpa16(sb + 128000 + tid * 16, offsrc + tid * 4);
    }
    cpa_commit_wait();
    __syncthreads();

    int lane = tid & 31;
    int w = tid >> 5;
    float* out = g_basis[dst_slot - 1] + (size_t)s * NN * FF;

    for (int n = w; n < NN; n += 16) {
        int b = soff[n], e = soff[n + 1];
        float acc;
        if (dir == 0) {                       // out[n] = sum sv[src]*w
            float a0 = 0.f, a1 = 0.f;
            int j = b;
            for (; j + 2 <= e; j += 2) {
                int2 e0 = __ldg(&g_adjA2[j]);
                int2 e1 = __ldg(&g_adjA2[j + 1]);
                a0 += sv[e0.x * 32 + lane] * __int_as_float(e0.y);
                a1 += sv[e1.x * 32 + lane] * __int_as_float(e1.y);
            }
            if (j < e) {
                int2 e0 = __ldg(&g_adjA2[j]);
                a0 += sv[e0.x * 32 + lane] * __int_as_float(e0.y);
            }
            acc = a0 + a1;
        } else {                              // out[n] = inv_deg_in[n] * sum sv[src]
            float a0 = 0.f, a1 = 0.f, a2 = 0.f, a3 = 0.f;
            int j = b;
            for (; j + 4 <= e; j += 4) {
                int s0 = __ldg(&g_adjB_src[j]);
                int s1 = __ldg(&g_adjB_src[j + 1]);
                int s2 = __ldg(&g_adjB_src[j + 2]);
                int s3 = __ldg(&g_adjB_src[j + 3]);
                a0 += sv[s0 * 32 + lane];
                a1 += sv[s1 * 32 + lane];
                a2 += sv[s2 * 32 + lane];
                a3 += sv[s3 * 32 + lane];
            }
            for (; j < e; j++)
                a0 += sv[__ldg(&g_adjB_src[j]) * 32 + lane];
            acc = ((a0 + a1) + (a2 + a3)) * g_inv_deg_in[n];
        }
        int f = half * 32 + lane;
        float r = (level == 1) ? acc : 2.0f * acc - prev[n * FF + f];
        out[n * FF + f] = r;
    }
}

// ---------------- mma.sync bf16 GEMM + fused gate/LN epilogue -----------------
// (round-7 proven version, unchanged)
#define SM_AHI 0
#define SM_ALO 16384
#define SM_BHI 32768
#define SM_BLO 49152
#define SM_TOTAL_GEMM 65536

__global__ void __launch_bounds__(256, 1) k_gemm_mma(const float* __restrict__ x,
                                                     const float* __restrict__ ln_g,
                                                     const float* __restrict__ ln_b) {
    extern __shared__ char smem[];
    uint32_t sb = smem_u32(smem);
    const int tid = threadIdx.x;
    const int wid = tid >> 5, lane = tid & 31;
    const int s = blockIdx.x >> 3;
    const int row0 = (blockIdx.x & 7) << 7;
    const int m0 = wid << 4;

    float acc[16][4];
    #pragma unroll
    for (int t = 0; t < 16; t++)
        #pragma unroll
        for (int c = 0; c < 4; c++) acc[t][c] = 0.0f;

    const uint32_t a_rowoff = (uint32_t)((m0 + (lane & 15)) * 128 + ((lane >> 4) * 16));
    const uint32_t b_rowoff = (uint32_t)((((lane >> 4) * 8 + (lane & 7)) * 128) + (((lane >> 3) & 1) * 16));

    for (int slot = 0; slot < 9; slot++) {
        __syncthreads();
        const float* plane = (slot == 0) ? (x + (size_t)s * NN * FF)
                                         : (g_basis[slot - 1] + (size_t)s * NN * FF);
        #pragma unroll
        for (int i = 0; i < 8; i++) {
            int j = tid + i * 256;
            int m = j >> 4, kq = j & 15;
            int node = row0 + m;
            float4 v = (node < NN) ? *(const float4*)(plane + (size_t)node * FF + kq * 4)
                                   : make_float4(0.f, 0.f, 0.f, 0.f);
            __nv_bfloat16 h0 = __float2bfloat16(v.x);
            __nv_bfloat16 h1 = __float2bfloat16(v.y);
            __nv_bfloat16 h2 = __float2bfloat16(v.z);
            __nv_bfloat16 h3 = __float2bfloat16(v.w);
            __nv_bfloat16 l0 = __float2bfloat16(v.x - __bfloat162float(h0));
            __nv_bfloat16 l1 = __float2bfloat16(v.y - __bfloat162float(h1));
            __nv_bfloat16 l2 = __float2bfloat16(v.z - __bfloat162float(h2));
            __nv_bfloat16 l3 = __float2bfloat16(v.w - __bfloat162float(h3));
            uint32_t off = SWZ128((uint32_t)(m * 128 + kq * 8));
            *(__nv_bfloat162*)(smem + SM_AHI + off)     = __halves2bfloat162(h0, h1);
            *(__nv_bfloat162*)(smem + SM_AHI + off + 4) = __halves2bfloat162(h2, h3);
            *(__nv_bfloat162*)(smem + SM_ALO + off)     = __halves2bfloat162(l0, l1);
            *(__nv_bfloat162*)(smem + SM_ALO + off + 4) = __halves2bfloat162(l2, l3);
        }
        {
            const uint4* srcH = (const uint4*)&g_Bpack[0][slot][0];
            const uint4* srcL = (const uint4*)&g_Bpack[1][slot][0];
            #pragma unroll
            for (int i = 0; i < 4; i++) {
                int j = tid + i * 256;
                ((uint4*)(smem + SM_BHI))[j] = srcH[j];
                ((uint4*)(smem + SM_BLO))[j] = srcL[j];
            }
        }
        __syncthreads();

        #pragma unroll
        for (int kk = 0; kk < 4; kk++) {
            const uint32_t kbase = kk * 32;
            uint32_t aAh[4], aAl[4];
            ldsm4(aAh, sb + SM_AHI + SWZ128(a_rowoff + kbase));
            ldsm4(aAl, sb + SM_ALO + SWZ128(a_rowoff + kbase));
            uint32_t bF[8][4];
            #pragma unroll
            for (int p = 0; p < 8; p++)
                ldsm4(bF[p], sb + SM_BHI + SWZ128(b_rowoff + p * 2048 + kbase));
            #pragma unroll
            for (int t = 0; t < 16; t++) {
                const uint32_t* bf = &bF[t >> 1][(t & 1) * 2];
                mma_bf16(acc[t], aAh, bf);     // Ahi * Bhi
                mma_bf16(acc[t], aAl, bf);     // Alo * Bhi
            }
            #pragma unroll
            for (int p = 0; p < 8; p++)
                ldsm4(bF[p], sb + SM_BLO + SWZ128(b_rowoff + p * 2048 + kbase));
            #pragma unroll
            for (int t = 0; t < 16; t++)
                mma_bf16(acc[t], aAh, &bF[t >> 1][(t & 1) * 2]);   // Ahi * Blo
        }
    }

    int q = lane & 3, rl = lane >> 2;
    #pragma unroll
    for (int h = 0; h < 2; h++) {
        float s1 = 0.f, s2 = 0.f;
        float vals[16];
        #pragma unroll
        for (int j = 0; j < 8; j++) {
            #pragma unroll
            for (int p = 0; p < 2; p++) {
                int col = j * 8 + q * 2 + p;
                float zc = acc[j][h * 2 + p] + g_bcat[col];
                float tc = acc[8 + j][h * 2 + p] + g_bcat[64 + col];
                float z = 1.0f / (1.0f + expf(-zc));
                float tt = tanhf(tc);
                float v = fmaxf((1.0f - z) * tt, 0.0f);
                vals[j * 2 + p] = v; s1 += v; s2 += v * v;
            }
        }
        s1 += __shfl_xor_sync(0xffffffffu, s1, 1);
        s1 += __shfl_xor_sync(0xffffffffu, s1, 2);
        s2 += __shfl_xor_sync(0xffffffffu, s2, 1);
        s2 += __shfl_xor_sync(0xffffffffu, s2, 2);
        float mu = s1 * (1.0f / 64.0f);
        float var = s2 * (1.0f / 64.0f) - mu * mu;
        float rstd = rsqrtf(var + LN_EPS);
        int node = row0 + m0 + rl + h * 8;
        if (node < NN) {
            float* o = g_h + ((size_t)s * NN + node) * FF;
            #pragma unroll
            for (int j = 0; j < 8; j++) {
                int col = j * 8 + q * 2;
                float2 w;
                w.x = (vals[j * 2 + 0] - mu) * rstd * ln_g[col] + ln_b[col];
                w.y = (vals[j * 2 + 1] - mu) * rstd * ln_g[col + 1] + ln_b[col + 1];
                *(float2*)(o + col) = w;
            }
        }
    }
}

// ---------------- final thin GEMM [16,768000] x [768000,10] -------------------
__global__ void __launch_bounds__(256) k_final1(const float* __restrict__ lin_w) {
    int chunk = blockIdx.x;
    int j0 = chunk * CHUNK_J;
    int tid = threadIdx.x;
    int bg = tid >> 6;
    int kl = tid & 63;
    float acc[4][10];
    #pragma unroll
    for (int bi = 0; bi < 4; bi++)
        #pragma unroll
        for (int c = 0; c < 10; c++) acc[bi][c] = 0.0f;

    for (int k = j0 + kl; k < j0 + CHUNK_J; k += 64) {
        float w[10];
        #pragma unroll
        for (int c = 0; c < 10; c++) w[c] = lin_w[(size_t)c * JTOT + k];
        #pragma unroll
        for (int bi = 0; bi < 4; bi++) {
            float h = g_h[(size_t)(bg * 4 + bi) * JTOT + k];
            #pragma unroll
            for (int c = 0; c < 10; c++) acc[bi][c] += h * w[c];
        }
    }
    __shared__ float red[256 * 40];
    #pragma unroll
    for (int bi = 0; bi < 4; bi++)
        #pragma unroll
        for (int c = 0; c < 10; c++) red[tid * 40 + bi * 10 + c] = acc[bi][c];
    __syncthreads();
    if (tid < 160) {
        int b = tid / 10, c = tid % 10;
        int bg2 = b >> 2, bi2 = b & 3;
        float sum = 0.0f;
        for (int l = 0; l < 64; l++)
            sum += red[(bg2 * 64 + l) * 40 + bi2 * 10 + c];
        g_partial[(chunk * BBATCH + b) * CC + c] = sum;
    }
}

__global__ void k_final2(const float* __restrict__ lin_b, float* __restrict__ out) {
    int i = threadIdx.x;
    if (i < BBATCH * CC) {
        int b = i / CC, c = i % CC;
        float s = lin_b[c];
        for (int ch = 0; ch < FCHUNKS; ch++)
            s += g_partial[(ch * BBATCH + b) * CC + c];
        out[b * CC + c] = s;
    }
}

// ---------------- launch ------------------------------------------------------
extern "C" void kernel_launch(void* const* d_in, const int* in_sizes, int n_in,
                              void* d_out, int out_size) {
    const float* x   = (const float*)d_in[0];
    const int*   ei  = (const int*)d_in[1];
    const float* Wz  = (const float*)d_in[2];
    const float* bz  = (const float*)d_in[3];
    // d_in[4]=W_r, d_in[5]=b_r provably unused (h0 == 0)
    const float* Wh  = (const float*)d_in[6];
    const float* bh  = (const float*)d_in[7];
    const float* lng = (const float*)d_in[8];
    const float* lnb = (const float*)d_in[9];
    const float* lw  = (const float*)d_in[10];
    const float* lb  = (const float*)d_in[11];
    float* out = (float*)d_out;

    cudaFuncSetAttribute(a_prop, cudaFuncAttributeMaxDynamicSharedMemorySize, PROP_SMEM);
    cudaFuncSetAttribute(k_build, cudaFuncAttributeMaxDynamicSharedMemorySize, EE * 8);
    cudaFuncSetAttribute(k_gemm_mma, cudaFuncAttributeMaxDynamicSharedMemorySize, SM_TOTAL_GEMM);

    k_zero_deg<<<1, 1024>>>();
    k_count<<<(EE + 255) / 256, 256>>>(ei);
    k_scan<<<1, 1024>>>();
    k_build<<<(NN + 7) / 8, 256, EE * 8>>>(ei);
    k_packW<<<(9 * 8192 + 255) / 256, 256>>>(Wz, bz, Wh, bh);

    for (int lvl = 1; lvl <= 4; lvl++)
        a_prop<<<dim3(SS, 2, 2), 512, PROP_SMEM>>>(x, lvl);

    k_gemm_mma<<<dim3(SS * 8), 256, SM_TOTAL_GEMM>>>(x, lng, lnb);
    k_final1<<<FCHUNKS, 256>>>(lw);
    k_final2<<<1, 192>>>(lb, out);
}

// round 11
// speedup vs baseline: 1.2148x; 1.0067x over previous
#include <cuda_runtime.h>
#include <cuda_bf16.h>
#include <math.h>
#include <stdint.h>

#define NN 1000
#define FF 64
#define SS 192          // B*T snapshots
#define EE 16000
#define CC 10
#define BBATCH 16
#define JTOT 768000     // T*N*F
#define LN_EPS 1e-5f
#define FCHUNKS 192
#define CHUNK_J 4000

// ---------------- scratch (static device globals; no allocation) -------------
__device__ float g_basis[8][SS * NN * FF];
__device__ float g_h[SS * NN * FF];
__device__ __nv_bfloat16 g_Bpack[2][9][8192];   // [hi/lo][slot][swizzled 128n x 64k]
__device__ float g_bcat[128];
__device__ int   g_deg_out[NN];
__device__ int   g_offA[NN + 8], g_offB[NN + 8];   // padded for 16B cp.async reads
__device__ int2  g_adjA2[EE];                    // prop_out: (src, bits(1/deg_out[src]))
__device__ int   g_adjB_src[EE];                 // prop_in : grouped by row, src=col
__device__ float g_inv_deg_in[NN];
__device__ float g_partial[FCHUNKS * BBATCH * CC];

// ---------------- helpers -----------------------------------------------------
__device__ __forceinline__ uint32_t smem_u32(const void* p) {
    uint32_t a;
    asm("{ .reg .u64 t; cvta.to.shared.u64 t, %1; cvt.u32.u64 %0, t; }" : "=r"(a) : "l"(p));
    return a;
}
#define SWZ128(o) ((o) ^ (((o) >> 3) & 0x70))

__device__ __forceinline__ void cpa16(uint32_t dst, const void* src) {
    asm volatile("cp.async.cg.shared.global [%0], [%1], 16;" :: "r"(dst), "l"(src));
}
__device__ __forceinline__ void cpa16z(uint32_t dst, const void* src, int srcsz) {
    asm volatile("cp.async.cg.shared.global [%0], [%1], 16, %2;"
                 :: "r"(dst), "l"(src), "r"(srcsz));
}
__device__ __forceinline__ void cpa_commit_wait() {
    asm volatile("cp.async.commit_group;" ::: "memory");
    asm volatile("cp.async.wait_group 0;" ::: "memory");
}

__device__ __forceinline__ void ldsm4(uint32_t* r, uint32_t addr) {
    asm volatile("ldmatrix.sync.aligned.m8n8.x4.shared.b16 {%0,%1,%2,%3}, [%4];"
        : "=r"(r[0]), "=r"(r[1]), "=r"(r[2]), "=r"(r[3]) : "r"(addr));
}

__device__ __forceinline__ void mma_bf16(float* d, const uint32_t* a, const uint32_t* b) {
    asm volatile(
        "mma.sync.aligned.m16n8k16.row.col.f32.bf16.bf16.f32 "
        "{%0,%1,%2,%3}, {%4,%5,%6,%7}, {%8,%9}, {%0,%1,%2,%3};"
        : "+f"(d[0]), "+f"(d[1]), "+f"(d[2]), "+f"(d[3])
        : "r"(a[0]), "r"(a[1]), "r"(a[2]), "r"(a[3]), "r"(b[0]), "r"(b[1]));
}

// ---------------- fused graph preprocessing (zero+count+scan, 1 block) --------
__global__ void k_pre(const int* __restrict__ ei) {
    __shared__ int sdo[NN], sdi[NN];
    __shared__ int sA[1024], sB[1024];
    int i = threadIdx.x;
    if (i < NN) { sdo[i] = 0; sdi[i] = 0; }
    __syncthreads();
    for (int e = i; e < EE; e += 1024) {
        atomicAdd(&sdo[ei[e]], 1);          // out-degree of src
        atomicAdd(&sdi[ei[EE + e]], 1);     // in-degree of dst
    }
    __syncthreads();
    int da = (i < NN) ? sdi[i] : 0;         // listA count[n] = deg_in[n]
    int db = (i < NN) ? sdo[i] : 0;         // listB count[n] = deg_out[n]
    sA[i] = da; sB[i] = db;
    __syncthreads();
    for (int off = 1; off < 1024; off <<= 1) {
        int va = (i >= off) ? sA[i - off] : 0;
        int vb = (i >= off) ? sB[i - off] : 0;
        __syncthreads();
        sA[i] += va; sB[i] += vb;
        __syncthreads();
    }
    if (i < NN) {
        g_deg_out[i] = sdo[i];
        g_offA[i] = sA[i] - da;
        g_offB[i] = sB[i] - db;
        g_inv_deg_in[i] = 1.0f / (float)da;
    }
    if (i == 0) { g_offA[NN] = sA[1023]; g_offB[NN] = sB[1023]; }
}

// deterministic CSR build: stage all edges in smem, one warp per node, ballot compaction
__global__ void k_build(const int* __restrict__ ei) {
    extern __shared__ int2 se[];                   // 16000 x 8B = 128KB
    int tid = threadIdx.x;
    for (int i = tid; i < EE; i += blockDim.x)
        se[i] = make_int2(ei[i], ei[EE + i]);
    __syncthreads();
    int warp = blockIdx.x * (blockDim.x >> 5) + (tid >> 5);
    int lane = tid & 31;
    if (warp >= NN) return;
    int n = warp;
    int pa = g_offA[n], pb = g_offB[n];
    for (int e0 = 0; e0 < EE; e0 += 32) {
        int2 rc = se[e0 + lane];
        unsigned mA = __ballot_sync(0xffffffffu, rc.y == n);
        unsigned mB = __ballot_sync(0xffffffffu, rc.x == n);
        if (rc.y == n) {
            int pos = pa + __popc(mA & ((1u << lane) - 1));
            g_adjA2[pos] = make_int2(rc.x, __float_as_int(1.0f / (float)g_deg_out[rc.x]));
        }
        if (rc.x == n) {
            int pos = pb + __popc(mB & ((1u << lane) - 1));
            g_adjB_src[pos] = rc.y;
        }
        pa += __popc(mA); pb += __popc(mB);
    }
}

// pack weights into bf16 hi/lo images (SW128-swizzled, [n][k] rows of 128B)
__global__ void k_packW(const float* __restrict__ Wz, const float* __restrict__ bz,
                        const float* __restrict__ Wh, const float* __restrict__ bh) {
    int i = blockIdx.x * blockDim.x + threadIdx.x;
    if (i < 128) g_bcat[i] = (i < 64) ? bz[i] : bh[i - 64];
    if (i >= 9 * 8192) return;
    int slot = i >> 13;
    int r = i & 8191;
    int n = r >> 6, k = r & 63;
    const float* W = (n < 64) ? Wz : Wh;
    int f = n & 63;
    float v;
    if (slot == 0) {
        v = W[(0 * 5 + 0) * 128 * 64 + k * 64 + f]
          + W[(1 * 5 + 0) * 128 * 64 + k * 64 + f];
    } else {
        int kc = (slot + 1) >> 1;
        int dir = (slot - 1) & 1;
        v = W[(dir * 5 + kc) * 128 * 64 + k * 64 + f];
    }
    __nv_bfloat16 hi = __float2bfloat16(v);
    __nv_bfloat16 lo = __float2bfloat16(v - __bfloat162float(hi));
    uint32_t off = SWZ128((uint32_t)(n * 128 + k * 2));
    g_Bpack[0][slot][off >> 1] = hi;
    g_Bpack[1][slot][off >> 1] = lo;
}

// ---------------- Chebyshev propagation (optimized gather) --------------------
// cp.async smem fill; CSR offsets in smem; int2-packed adjacency; unrolled
// multi-accumulator edge loops. Recurrence: both dirs subtract OUT-dir prev.
#define PROP_SMEM (32000 * 4 + 1008 * 4)

__global__ void __launch_bounds__(512, 1) a_prop(const float* __restrict__ x, int level) {
    extern __shared__ float sv[];                  // [32000] values
    int* soff = (int*)(sv + 32000);                // [1008] CSR offsets (this dir)
    int s = blockIdx.x, dir = blockIdx.y, half = blockIdx.z;
    int dst_slot = 2 * level - 1 + dir;
    const float* src;
    const float* prev = nullptr;
    if (level == 1) {
        src = x + (size_t)s * NN * FF;
    } else {
        int ssrc = 2 * (level - 1) - 1 + dir;
        src = g_basis[ssrc - 1] + (size_t)s * NN * FF;
        if (level == 2) prev = x + (size_t)s * NN * FF;
        else prev = g_basis[(2 * (level - 2) - 1) - 1] + (size_t)s * NN * FF;
    }
    uint32_t sb = smem_u32(sv);
    int tid = threadIdx.x;
    #pragma unroll
    for (int it = 0; it < 16; it++) {
        int i = tid + it * 512;
        if (i < 8000) {
            int n = i >> 3, q = i & 7;
            cpa16(sb + (uint32_t)(n * 128 + q * 16),
                  src + (size_t)n * FF + half * 32 + q * 4);
        }
    }
    {
        const int* offsrc = dir ? g_offB : g_offA;
        if (tid < 251)
            cpa16(sb + 128000 + tid * 16, offsrc + tid * 4);
    }
    cpa_commit_wait();
    __syncthreads();

    int lane = tid & 31;
    int w = tid >> 5;
    float* out = g_basis[dst_slot - 1] + (size_t)s * NN * FF;

    for (int n = w; n < NN; n += 16) {
        int b = soff[n], e = soff[n + 1];
        float acc;
        if (dir == 0) {
            float a0 = 0.f, a1 = 0.f;
            int j = b;
            for (; j + 2 <= e; j += 2) {
                int2 e0 = __ldg(&g_adjA2[j]);
                int2 e1 = __ldg(&g_adjA2[j + 1]);
                a0 += sv[e0.x * 32 + lane] * __int_as_float(e0.y);
                a1 += sv[e1.x * 32 + lane] * __int_as_float(e1.y);
            }
            if (j < e) {
                int2 e0 = __ldg(&g_adjA2[j]);
                a0 += sv[e0.x * 32 + lane] * __int_as_float(e0.y);
            }
            acc = a0 + a1;
        } else {
            float a0 = 0.f, a1 = 0.f, a2 = 0.f, a3 = 0.f;
            int j = b;
            for (; j + 4 <= e; j += 4) {
                int s0 = __ldg(&g_adjB_src[j]);
                int s1 = __ldg(&g_adjB_src[j + 1]);
                int s2 = __ldg(&g_adjB_src[j + 2]);
                int s3 = __ldg(&g_adjB_src[j + 3]);
                a0 += sv[s0 * 32 + lane];
                a1 += sv[s1 * 32 + lane];
                a2 += sv[s2 * 32 + lane];
                a3 += sv[s3 * 32 + lane];
            }
            for (; j < e; j++)
                a0 += sv[__ldg(&g_adjB_src[j]) * 32 + lane];
            acc = ((a0 + a1) + (a2 + a3)) * g_inv_deg_in[n];
        }
        int f = half * 32 + lane;
        float r = (level == 1) ? acc : 2.0f * acc - prev[n * FF + f];
        out[n * FF + f] = r;
    }
}

// ---------------- pipelined mma.sync bf16 GEMM + fused gate/LN epilogue -------
// cp.async double-buffers raw fp32 A (32KB) and bf16 B images (32KB) per slot;
// A converted fp32->bf16 hi/lo smem->smem. 3-pass bf16 split, fp32 accum.
#define SM_AF32 0               // 2 x 32768
#define SM_AHI  65536           // 16384
#define SM_ALO  81920           // 16384
#define SM_B    98304           // 2 x 32768 (hi at +0, lo at +16384)
#define SM_TOTAL_GEMM 163840

__global__ void __launch_bounds__(256, 1) k_gemm_mma(const float* __restrict__ x,
                                                     const float* __restrict__ ln_g,
                                                     const float* __restrict__ ln_b) {
    extern __shared__ char smem[];
    uint32_t sb = smem_u32(smem);
    const int tid = threadIdx.x;
    const int wid = tid >> 5, lane = tid & 31;
    const int s = blockIdx.x >> 3;
    const int row0 = (blockIdx.x & 7) << 7;
    const int m0 = wid << 4;

    float acc[16][4];
    #pragma unroll
    for (int t = 0; t < 16; t++)
        #pragma unroll
        for (int c = 0; c < 4; c++) acc[t][c] = 0.0f;

    const uint32_t a_rowoff = (uint32_t)((m0 + (lane & 15)) * 128 + ((lane >> 4) * 16));
    const uint32_t b_rowoff = (uint32_t)((((lane >> 4) * 8 + (lane & 7)) * 128) + (((lane >> 3) & 1) * 16));

    auto issue = [&](int slot, int buf) {
        const float* plane = (slot == 0) ? (x + (size_t)s * NN * FF)
                                         : (g_basis[slot - 1] + (size_t)s * NN * FF);
        #pragma unroll
        for (int i = 0; i < 8; i++) {
            int j = tid + i * 256;                 // 2048 16B chunks of A fp32
            int node = row0 + (j >> 4);
            cpa16z(sb + SM_AF32 + buf * 32768 + j * 16,
                   plane + (size_t)node * FF + (j & 15) * 4, node < NN ? 16 : 0);
        }
        const char* bh = (const char*)&g_Bpack[0][slot][0];
        const char* bl = (const char*)&g_Bpack[1][slot][0];
        #pragma unroll
        for (int i = 0; i < 4; i++) {
            int j = tid + i * 256;                 // 1024 chunks each
            cpa16(sb + SM_B + buf * 32768 + j * 16, bh + j * 16);
            cpa16(sb + SM_B + buf * 32768 + 16384 + j * 16, bl + j * 16);
        }
        asm volatile("cp.async.commit_group;" ::: "memory");
    };

    issue(0, 0);
    for (int slot = 0; slot < 9; slot++) {
        int buf = slot & 1;
        if (slot < 8) {
            issue(slot + 1, buf ^ 1);
            asm volatile("cp.async.wait_group 1;" ::: "memory");
        } else {
            asm volatile("cp.async.wait_group 0;" ::: "memory");
        }
        __syncthreads();
        // convert A fp32 (staging) -> bf16 hi/lo swizzled
        #pragma unroll
        for (int i = 0; i < 8; i++) {
            int j = tid + i * 256;
            int m = j >> 4, kq = j & 15;
            float4 v = *(const float4*)(smem + SM_AF32 + buf * 32768 + j * 16);
            __nv_bfloat16 h0 = __float2bfloat16(v.x);
            __nv_bfloat16 h1 = __float2bfloat16(v.y);
            __nv_bfloat16 h2 = __float2bfloat16(v.z);
            __nv_bfloat16 h3 = __float2bfloat16(v.w);
            __nv_bfloat16 l0 = __float2bfloat16(v.x - __bfloat162float(h0));
            __nv_bfloat16 l1 = __float2bfloat16(v.y - __bfloat162float(h1));
            __nv_bfloat16 l2 = __float2bfloat16(v.z - __bfloat162float(h2));
            __nv_bfloat16 l3 = __float2bfloat16(v.w - __bfloat162float(h3));
            uint32_t off = SWZ128((uint32_t)(m * 128 + kq * 8));
            *(__nv_bfloat162*)(smem + SM_AHI + off)     = __halves2bfloat162(h0, h1);
            *(__nv_bfloat162*)(smem + SM_AHI + off + 4) = __halves2bfloat162(h2, h3);
            *(__nv_bfloat162*)(smem + SM_ALO + off)     = __halves2bfloat162(l0, l1);
            *(__nv_bfloat162*)(smem + SM_ALO + off + 4) = __halves2bfloat162(l2, l3);
        }
        __syncthreads();

        uint32_t bBH = sb + SM_B + buf * 32768;
        uint32_t bBL = bBH + 16384;
        #pragma unroll
        for (int kk = 0; kk < 4; kk++) {
            const uint32_t kbase = kk * 32;
            uint32_t aAh[4], aAl[4];
            ldsm4(aAh, sb + SM_AHI + SWZ128(a_rowoff + kbase));
            ldsm4(aAl, sb + SM_ALO + SWZ128(a_rowoff + kbase));
            uint32_t bF[8][4];
            #pragma unroll
            for (int p = 0; p < 8; p++)
                ldsm4(bF[p], bBH + SWZ128(b_rowoff + p * 2048 + kbase));
            #pragma unroll
            for (int t = 0; t < 16; t++) {
                const uint32_t* bf = &bF[t >> 1][(t & 1) * 2];
                mma_bf16(acc[t], aAh, bf);     // Ahi * Bhi
                mma_bf16(acc[t], aAl, bf);     // Alo * Bhi
            }
            #pragma unroll
            for (int p = 0; p < 8; p++)
                ldsm4(bF[p], bBL + SWZ128(b_rowoff + p * 2048 + kbase));
            #pragma unroll
            for (int t = 0; t < 16; t++)
                mma_bf16(acc[t], aAh, &bF[t >> 1][(t & 1) * 2]);   // Ahi * Blo
        }
        __syncthreads();   // protect staged buffers from next iteration's issue
    }

    // fused epilogue: gates + relu + LayerNorm (register/shfl local, __expf)
    int q = lane & 3, rl = lane >> 2;
    #pragma unroll
    for (int h = 0; h < 2; h++) {
        float s1 = 0.f, s2 = 0.f;
        float vals[16];
        #pragma unroll
        for (int j = 0; j < 8; j++) {
            #pragma unroll
            for (int p = 0; p < 2; p++) {
                int col = j * 8 + q * 2 + p;
                float zc = acc[j][h * 2 + p] + g_bcat[col];
                float tc = acc[8 + j][h * 2 + p] + g_bcat[64 + col];
                float z = 1.0f / (1.0f + __expf(-zc));
                float tt = 1.0f - 2.0f / (__expf(2.0f * tc) + 1.0f);
                float v = fmaxf((1.0f - z) * tt, 0.0f);
                vals[j * 2 + p] = v; s1 += v; s2 += v * v;
            }
        }
        s1 += __shfl_xor_sync(0xffffffffu, s1, 1);
        s1 += __shfl_xor_sync(0xffffffffu, s1, 2);
        s2 += __shfl_xor_sync(0xffffffffu, s2, 1);
        s2 += __shfl_xor_sync(0xffffffffu, s2, 2);
        float mu = s1 * (1.0f / 64.0f);
        float var = s2 * (1.0f / 64.0f) - mu * mu;
        float rstd = rsqrtf(var + LN_EPS);
        int node = row0 + m0 + rl + h * 8;
        if (node < NN) {
            float* o = g_h + ((size_t)s * NN + node) * FF;
            #pragma unroll
            for (int j = 0; j < 8; j++) {
                int col = j * 8 + q * 2;
                float2 w;
                w.x = (vals[j * 2 + 0] - mu) * rstd * ln_g[col] + ln_b[col];
                w.y = (vals[j * 2 + 1] - mu) * rstd * ln_g[col + 1] + ln_b[col + 1];
                *(float2*)(o + col) = w;
            }
        }
    }
}

// ---------------- final thin GEMM [16,768000] x [768000,10] -------------------
__global__ void __launch_bounds__(256) k_final1(const float* __restrict__ lin_w) {
    int chunk = blockIdx.x;
    int j0 = chunk * CHUNK_J;
    int tid = threadIdx.x;
    int bg = tid >> 6;
    int kl = tid & 63;
    float acc[4][10];
    #pragma unroll
    for (int bi = 0; bi < 4; bi++)
        #pragma unroll
        for (int c = 0; c < 10; c++) acc[bi][c] = 0.0f;

    for (int k = j0 + kl; k < j0 + CHUNK_J; k += 64) {
        float w[10];
        #pragma unroll
        for (int c = 0; c < 10; c++) w[c] = lin_w[(size_t)c * JTOT + k];
        #pragma unroll
        for (int bi = 0; bi < 4; bi++) {
            float h = g_h[(size_t)(bg * 4 + bi) * JTOT + k];
            #pragma unroll
            for (int c = 0; c < 10; c++) acc[bi][c] += h * w[c];
        }
    }
    __shared__ float red[256 * 40];
    #pragma unroll
    for (int bi = 0; bi < 4; bi++)
        #pragma unroll
        for (int c = 0; c < 10; c++) red[tid * 40 + bi * 10 + c] = acc[bi][c];
    __syncthreads();
    if (tid < 160) {
        int b = tid / 10, c = tid % 10;
        int bg2 = b >> 2, bi2 = b & 3;
        float sum = 0.0f;
        for (int l = 0; l < 64; l++)
            sum += red[(bg2 * 64 + l) * 40 + bi2 * 10 + c];
        g_partial[(chunk * BBATCH + b) * CC + c] = sum;
    }
}

__global__ void k_final2(const float* __restrict__ lin_b, float* __restrict__ out) {
    int i = threadIdx.x;
    if (i < BBATCH * CC) {
        int b = i / CC, c = i % CC;
        float s = lin_b[c];
        for (int ch = 0; ch < FCHUNKS; ch++)
            s += g_partial[(ch * BBATCH + b) * CC + c];
        out[b * CC + c] = s;
    }
}

// ---------------- launch ------------------------------------------------------
extern "C" void kernel_launch(void* const* d_in, const int* in_sizes, int n_in,
                              void* d_out, int out_size) {
    const float* x   = (const float*)d_in[0];
    const int*   ei  = (const int*)d_in[1];
    const float* Wz  = (const float*)d_in[2];
    const float* bz  = (const float*)d_in[3];
    // d_in[4]=W_r, d_in[5]=b_r provably unused (h0 == 0)
    const float* Wh  = (const float*)d_in[6];
    const float* bh  = (const float*)d_in[7];
    const float* lng = (const float*)d_in[8];
    const float* lnb = (const float*)d_in[9];
    const float* lw  = (const float*)d_in[10];
    const float* lb  = (const float*)d_in[11];
    float* out = (float*)d_out;

    cudaFuncSetAttribute(a_prop, cudaFuncAttributeMaxDynamicSharedMemorySize, PROP_SMEM);
    cudaFuncSetAttribute(k_build, cudaFuncAttributeMaxDynamicSharedMemorySize, EE * 8);
    cudaFuncSetAttribute(k_gemm_mma, cudaFuncAttributeMaxDynamicSharedMemorySize, SM_TOTAL_GEMM);

    k_packW<<<(9 * 8192 + 255) / 256, 256>>>(Wz, bz, Wh, bh);   // launch 1
    k_pre<<<1, 1024>>>(ei);                                      // launch 2
    k_build<<<(NN + 7) / 8, 256, EE * 8>>>(ei);                  // launch 3

    for (int lvl = 1; lvl <= 4; lvl++)                           // launches 4-7
        a_prop<<<dim3(SS, 2, 2), 512, PROP_SMEM>>>(x, lvl);

    k_gemm_mma<<<dim3(SS * 8), 256, SM_TOTAL_GEMM>>>(x, lng, lnb);
    k_final1<<<FCHUNKS, 256>>>(lw);
    k_final2<<<1, 192>>>(lb, out);
}

// round 12
// speedup vs baseline: 1.9548x; 1.6092x over previous
#include <cuda_runtime.h>
#include <cuda_bf16.h>
#include <math.h>
#include <stdint.h>

#define NN 1000
#define FF 64
#define SS 192          // B*T snapshots
#define EE 16000
#define CC 10
#define BBATCH 16
#define JTOT 768000     // T*N*F
#define LN_EPS 1e-5f
#define FCHUNKS 192
#define CHUNK_J 4000

// ---------------- scratch (static device globals; no allocation) -------------
__device__ float g_basis[8][SS * NN * FF];
__device__ float g_h[SS * NN * FF];
__device__ __nv_bfloat16 g_Bpack[2][9][8192];   // [hi/lo][slot][swizzled 128n x 64k]
__device__ float g_bcat[128];
__device__ int   g_offA[NN + 8], g_offB[NN + 8];   // padded for 16B cp.async reads
__device__ uint16_t g_adjA16[EE + 8];            // prop_out srcs (grouped by dst)
__device__ uint16_t g_adjB16[EE + 8];            // prop_in  srcs (grouped by row)
__device__ float g_invdeg_out[NN];
__device__ float g_inv_deg_in[NN];
__device__ float g_partial[FCHUNKS * BBATCH * CC];

// ---------------- helpers -----------------------------------------------------
__device__ __forceinline__ uint32_t smem_u32(const void* p) {
    uint32_t a;
    asm("{ .reg .u64 t; cvta.to.shared.u64 t, %1; cvt.u32.u64 %0, t; }" : "=r"(a) : "l"(p));
    return a;
}
#define SWZ128(o) ((o) ^ (((o) >> 3) & 0x70))

__device__ __forceinline__ void cpa16(uint32_t dst, const void* src) {
    asm volatile("cp.async.cg.shared.global [%0], [%1], 16;" :: "r"(dst), "l"(src));
}
__device__ __forceinline__ void cpa16z(uint32_t dst, const void* src, int srcsz) {
    asm volatile("cp.async.cg.shared.global [%0], [%1], 16, %2;"
                 :: "r"(dst), "l"(src), "r"(srcsz));
}
__device__ __forceinline__ void cpa_commit_wait() {
    asm volatile("cp.async.commit_group;" ::: "memory");
    asm volatile("cp.async.wait_group 0;" ::: "memory");
}

__device__ __forceinline__ void ldsm4(uint32_t* r, uint32_t addr) {
    asm volatile("ldmatrix.sync.aligned.m8n8.x4.shared.b16 {%0,%1,%2,%3}, [%4];"
        : "=r"(r[0]), "=r"(r[1]), "=r"(r[2]), "=r"(r[3]) : "r"(addr));
}

__device__ __forceinline__ void mma_bf16(float* d, const uint32_t* a, const uint32_t* b) {
    asm volatile(
        "mma.sync.aligned.m16n8k16.row.col.f32.bf16.bf16.f32 "
        "{%0,%1,%2,%3}, {%4,%5,%6,%7}, {%8,%9}, {%0,%1,%2,%3};"
        : "+f"(d[0]), "+f"(d[1]), "+f"(d[2]), "+f"(d[3])
        : "r"(a[0]), "r"(a[1]), "r"(a[2]), "r"(a[3]), "r"(b[0]), "r"(b[1]));
}

// ---------------- fused graph preprocessing (zero+count+scan, 1 block) --------
__global__ void k_pre(const int* __restrict__ ei) {
    __shared__ int sdo[NN], sdi[NN];
    __shared__ int sA[1024], sB[1024];
    int i = threadIdx.x;
    if (i < NN) { sdo[i] = 0; sdi[i] = 0; }
    __syncthreads();
    for (int e = i; e < EE; e += 1024) {
        atomicAdd(&sdo[ei[e]], 1);          // out-degree of src
        atomicAdd(&sdi[ei[EE + e]], 1);     // in-degree of dst
    }
    __syncthreads();
    int da = (i < NN) ? sdi[i] : 0;         // listA count[n] = deg_in[n]
    int db = (i < NN) ? sdo[i] : 0;         // listB count[n] = deg_out[n]
    sA[i] = da; sB[i] = db;
    __syncthreads();
    for (int off = 1; off < 1024; off <<= 1) {
        int va = (i >= off) ? sA[i - off] : 0;
        int vb = (i >= off) ? sB[i - off] : 0;
        __syncthreads();
        sA[i] += va; sB[i] += vb;
        __syncthreads();
    }
    if (i < NN) {
        g_offA[i] = sA[i] - da;
        g_offB[i] = sB[i] - db;
        g_inv_deg_in[i] = 1.0f / (float)da;
        g_invdeg_out[i] = 1.0f / (float)sdo[i];
    }
    if (i == 0) { g_offA[NN] = sA[1023]; g_offB[NN] = sB[1023]; }
}

// deterministic CSR build: stage all edges in smem, one warp per node, ballot compaction
__global__ void k_build(const int* __restrict__ ei) {
    extern __shared__ int2 se[];                   // 16000 x 8B = 128KB
    int tid = threadIdx.x;
    for (int i = tid; i < EE; i += blockDim.x)
        se[i] = make_int2(ei[i], ei[EE + i]);
    __syncthreads();
    int warp = blockIdx.x * (blockDim.x >> 5) + (tid >> 5);
    int lane = tid & 31;
    if (warp >= NN) return;
    int n = warp;
    int pa = g_offA[n], pb = g_offB[n];
    for (int e0 = 0; e0 < EE; e0 += 32) {
        int2 rc = se[e0 + lane];
        unsigned mA = __ballot_sync(0xffffffffu, rc.y == n);
        unsigned mB = __ballot_sync(0xffffffffu, rc.x == n);
        if (rc.y == n) {
            int pos = pa + __popc(mA & ((1u << lane) - 1));
            g_adjA16[pos] = (uint16_t)rc.x;
        }
        if (rc.x == n) {
            int pos = pb + __popc(mB & ((1u << lane) - 1));
            g_adjB16[pos] = (uint16_t)rc.y;
        }
        pa += __popc(mA); pb += __popc(mB);
    }
}

// pack weights into bf16 hi/lo images (SW128-swizzled, [n][k] rows of 128B)
__global__ void k_packW(const float* __restrict__ Wz, const float* __restrict__ bz,
                        const float* __restrict__ Wh, const float* __restrict__ bh) {
    int i = blockIdx.x * blockDim.x + threadIdx.x;
    if (i < 128) g_bcat[i] = (i < 64) ? bz[i] : bh[i - 64];
    if (i >= 9 * 8192) return;
    int slot = i >> 13;
    int r = i & 8191;
    int n = r >> 6, k = r & 63;
    const float* W = (n < 64) ? Wz : Wh;
    int f = n & 63;
    float v;
    if (slot == 0) {
        v = W[(0 * 5 + 0) * 128 * 64 + k * 64 + f]
          + W[(1 * 5 + 0) * 128 * 64 + k * 64 + f];
    } else {
        int kc = (slot + 1) >> 1;
        int dir = (slot - 1) & 1;
        v = W[(dir * 5 + kc) * 128 * 64 + k * 64 + f];
    }
    __nv_bfloat16 hi = __float2bfloat16(v);
    __nv_bfloat16 lo = __float2bfloat16(v - __bfloat162float(hi));
    uint32_t off = SWZ128((uint32_t)(n * 128 + k * 2));
    g_Bpack[0][slot][off >> 1] = hi;
    g_Bpack[1][slot][off >> 1] = lo;
}

// ---------------- Chebyshev propagation (all-smem gather) ---------------------
// Values (125KB) + uint16 adjacency (32KB) + offsets (4KB) + inv-deg (4KB)
// all cp.async'd into one 168KB smem block; edge loop is pure LDS+FFMA.
// Recurrence: both dirs subtract the OUT-direction previous term.
#define SV_OFF   0          // 32000 floats
#define ADJ_OFF  128000     // 16000 uint16
#define OFF_OFF  160000     // 1008 ints
#define INV_OFF  164032     // 1000 floats
#define PROP_SMEM 168032

__global__ void __launch_bounds__(1024, 1) a_prop(const float* __restrict__ x, int level) {
    extern __shared__ float sv[];
    uint16_t* sadj = (uint16_t*)((char*)sv + ADJ_OFF);
    int* soff = (int*)((char*)sv + OFF_OFF);
    float* sinv = (float*)((char*)sv + INV_OFF);
    int s = blockIdx.x, dir = blockIdx.y, half = blockIdx.z;
    int dst_slot = 2 * level - 1 + dir;
    const float* src;
    const float* prev = nullptr;
    if (level == 1) {
        src = x + (size_t)s * NN * FF;
    } else {
        int ssrc = 2 * (level - 1) - 1 + dir;
        src = g_basis[ssrc - 1] + (size_t)s * NN * FF;
        if (level == 2) prev = x + (size_t)s * NN * FF;
        else prev = g_basis[(2 * (level - 2) - 1) - 1] + (size_t)s * NN * FF;
    }
    uint32_t sb = smem_u32(sv);
    int tid = threadIdx.x;
    // values: 8000 x 16B chunks
    #pragma unroll
    for (int it = 0; it < 8; it++) {
        int i = tid + it * 1024;
        if (i < 8000) {
            int n = i >> 3, q = i & 7;
            cpa16(sb + (uint32_t)(n * 128 + q * 16),
                  src + (size_t)n * FF + half * 32 + q * 4);
        }
    }
    // adjacency: 2000 x 16B chunks
    {
        const uint16_t* adj = dir ? g_adjB16 : g_adjA16;
        #pragma unroll
        for (int it = 0; it < 2; it++) {
            int i = tid + it * 1024;
            if (i < 2000)
                cpa16(sb + ADJ_OFF + i * 16, adj + i * 8);
        }
    }
    // offsets: 251 chunks; inv-deg: 250 chunks (disjoint thread ranges)
    if (tid < 251) {
        const int* offsrc = dir ? g_offB : g_offA;
        cpa16(sb + OFF_OFF + tid * 16, offsrc + tid * 4);
    }
    if (tid >= 512 && tid < 762) {
        const float* invsrc = dir ? g_inv_deg_in : g_invdeg_out;
        int i = tid - 512;
        cpa16(sb + INV_OFF + i * 16, invsrc + i * 4);
    }
    cpa_commit_wait();
    __syncthreads();

    int lane = tid & 31;
    int w = tid >> 5;                     // 32 warps
    float* out = g_basis[dst_slot - 1] + (size_t)s * NN * FF;

    for (int n = w; n < NN; n += 32) {
        int b = soff[n], e = soff[n + 1];
        float acc;
        if (dir == 0) {                   // out[n] = sum sv[src] / deg_out[src]
            float a0 = 0.f, a1 = 0.f, a2 = 0.f, a3 = 0.f;
            int j = b;
            for (; j + 4 <= e; j += 4) {
                int s0 = sadj[j], s1 = sadj[j + 1], s2 = sadj[j + 2], s3 = sadj[j + 3];
                a0 += sv[s0 * 32 + lane] * sinv[s0];
                a1 += sv[s1 * 32 + lane] * sinv[s1];
                a2 += sv[s2 * 32 + lane] * sinv[s2];
                a3 += sv[s3 * 32 + lane] * sinv[s3];
            }
            for (; j < e; j++) {
                int s0 = sadj[j];
                a0 += sv[s0 * 32 + lane] * sinv[s0];
            }
            acc = (a0 + a1) + (a2 + a3);
        } else {                          // out[n] = inv_deg_in[n] * sum sv[src]
            float a0 = 0.f, a1 = 0.f, a2 = 0.f, a3 = 0.f;
            int j = b;
            for (; j + 4 <= e; j += 4) {
                int s0 = sadj[j], s1 = sadj[j + 1], s2 = sadj[j + 2], s3 = sadj[j + 3];
                a0 += sv[s0 * 32 + lane];
                a1 += sv[s1 * 32 + lane];
                a2 += sv[s2 * 32 + lane];
                a3 += sv[s3 * 32 + lane];
            }
            for (; j < e; j++)
                a0 += sv[sadj[j] * 32 + lane];
            acc = ((a0 + a1) + (a2 + a3)) * sinv[n];
        }
        int f = half * 32 + lane;
        float r = (level == 1) ? acc : 2.0f * acc - prev[n * FF + f];
        out[n * FF + f] = r;
    }
}

// ---------------- pipelined mma.sync bf16 GEMM + fused gate/LN epilogue -------
#define SM_AF32 0               // 2 x 32768
#define SM_AHI  65536           // 16384
#define SM_ALO  81920           // 16384
#define SM_B    98304           // 2 x 32768 (hi at +0, lo at +16384)
#define SM_TOTAL_GEMM 163840

__global__ void __launch_bounds__(256, 1) k_gemm_mma(const float* __restrict__ x,
                                                     const float* __restrict__ ln_g,
                                                     const float* __restrict__ ln_b) {
    extern __shared__ char smem[];
    uint32_t sb = smem_u32(smem);
    const int tid = threadIdx.x;
    const int wid = tid >> 5, lane = tid & 31;
    const int s = blockIdx.x >> 3;
    const int row0 = (blockIdx.x & 7) << 7;
    const int m0 = wid << 4;

    float acc[16][4];
    #pragma unroll
    for (int t = 0; t < 16; t++)
        #pragma unroll
        for (int c = 0; c < 4; c++) acc[t][c] = 0.0f;

    const uint32_t a_rowoff = (uint32_t)((m0 + (lane & 15)) * 128 + ((lane >> 4) * 16));
    const uint32_t b_rowoff = (uint32_t)((((lane >> 4) * 8 + (lane & 7)) * 128) + (((lane >> 3) & 1) * 16));

    auto issue = [&](int slot, int buf) {
        const float* plane = (slot == 0) ? (x + (size_t)s * NN * FF)
                                         : (g_basis[slot - 1] + (size_t)s * NN * FF);
        #pragma unroll
        for (int i = 0; i < 8; i++) {
            int j = tid + i * 256;
            int node = row0 + (j >> 4);
            cpa16z(sb + SM_AF32 + buf * 32768 + j * 16,
                   plane + (size_t)node * FF + (j & 15) * 4, node < NN ? 16 : 0);
        }
        const char* bh = (const char*)&g_Bpack[0][slot][0];
        const char* bl = (const char*)&g_Bpack[1][slot][0];
        #pragma unroll
        for (int i = 0; i < 4; i++) {
            int j = tid + i * 256;
            cpa16(sb + SM_B + buf * 32768 + j * 16, bh + j * 16);
            cpa16(sb + SM_B + buf * 32768 + 16384 + j * 16, bl + j * 16);
        }
        asm volatile("cp.async.commit_group;" ::: "memory");
    };

    issue(0, 0);
    for (int slot = 0; slot < 9; slot++) {
        int buf = slot & 1;
        if (slot < 8) {
            issue(slot + 1, buf ^ 1);
            asm volatile("cp.async.wait_group 1;" ::: "memory");
        } else {
            asm volatile("cp.async.wait_group 0;" ::: "memory");
        }
        __syncthreads();
        #pragma unroll
        for (int i = 0; i < 8; i++) {
            int j = tid + i * 256;
            int m = j >> 4, kq = j & 15;
            float4 v = *(const float4*)(smem + SM_AF32 + buf * 32768 + j * 16);
            __nv_bfloat16 h0 = __float2bfloat16(v.x);
            __nv_bfloat16 h1 = __float2bfloat16(v.y);
            __nv_bfloat16 h2 = __float2bfloat16(v.z);
            __nv_bfloat16 h3 = __float2bfloat16(v.w);
            __nv_bfloat16 l0 = __float2bfloat16(v.x - __bfloat162float(h0));
            __nv_bfloat16 l1 = __float2bfloat16(v.y - __bfloat162float(h1));
            __nv_bfloat16 l2 = __float2bfloat16(v.z - __bfloat162float(h2));
            __nv_bfloat16 l3 = __float2bfloat16(v.w - __bfloat162float(h3));
            uint32_t off = SWZ128((uint32_t)(m * 128 + kq * 8));
            *(__nv_bfloat162*)(smem + SM_AHI + off)     = __halves2bfloat162(h0, h1);
            *(__nv_bfloat162*)(smem + SM_AHI + off + 4) = __halves2bfloat162(h2, h3);
            *(__nv_bfloat162*)(smem + SM_ALO + off)     = __halves2bfloat162(l0, l1);
            *(__nv_bfloat162*)(smem + SM_ALO + off + 4) = __halves2bfloat162(l2, l3);
        }
        __syncthreads();

        uint32_t bBH = sb + SM_B + buf * 32768;
        uint32_t bBL = bBH + 16384;
        #pragma unroll
        for (int kk = 0; kk < 4; kk++) {
            const uint32_t kbase = kk * 32;
            uint32_t aAh[4], aAl[4];
            ldsm4(aAh, sb + SM_AHI + SWZ128(a_rowoff + kbase));
            ldsm4(aAl, sb + SM_ALO + SWZ128(a_rowoff + kbase));
            uint32_t bF[8][4];
            #pragma unroll
            for (int p = 0; p < 8; p++)
                ldsm4(bF[p], bBH + SWZ128(b_rowoff + p * 2048 + kbase));
            #pragma unroll
            for (int t = 0; t < 16; t++) {
                const uint32_t* bf = &bF[t >> 1][(t & 1) * 2];
                mma_bf16(acc[t], aAh, bf);     // Ahi * Bhi
                mma_bf16(acc[t], aAl, bf);     // Alo * Bhi
            }
            #pragma unroll
            for (int p = 0; p < 8; p++)
                ldsm4(bF[p], bBL + SWZ128(b_rowoff + p * 2048 + kbase));
            #pragma unroll
            for (int t = 0; t < 16; t++)
                mma_bf16(acc[t], aAh, &bF[t >> 1][(t & 1) * 2]);   // Ahi * Blo
        }
        __syncthreads();
    }

    // fused epilogue: gates + relu + LayerNorm (register/shfl local, __expf)
    int q = lane & 3, rl = lane >> 2;
    #pragma unroll
    for (int h = 0; h < 2; h++) {
        float s1 = 0.f, s2 = 0.f;
        float vals[16];
        #pragma unroll
        for (int j = 0; j < 8; j++) {
            #pragma unroll
            for (int p = 0; p < 2; p++) {
                int col = j * 8 + q * 2 + p;
                float zc = acc[j][h * 2 + p] + g_bcat[col];
                float tc = acc[8 + j][h * 2 + p] + g_bcat[64 + col];
                float z = 1.0f / (1.0f + __expf(-zc));
                float tt = 1.0f - 2.0f / (__expf(2.0f * tc) + 1.0f);
                float v = fmaxf((1.0f - z) * tt, 0.0f);
                vals[j * 2 + p] = v; s1 += v; s2 += v * v;
            }
        }
        s1 += __shfl_xor_sync(0xffffffffu, s1, 1);
        s1 += __shfl_xor_sync(0xffffffffu, s1, 2);
        s2 += __shfl_xor_sync(0xffffffffu, s2, 1);
        s2 += __shfl_xor_sync(0xffffffffu, s2, 2);
        float mu = s1 * (1.0f / 64.0f);
        float var = s2 * (1.0f / 64.0f) - mu * mu;
        float rstd = rsqrtf(var + LN_EPS);
        int node = row0 + m0 + rl + h * 8;
        if (node < NN) {
            float* o = g_h + ((size_t)s * NN + node) * FF;
            #pragma unroll
            for (int j = 0; j < 8; j++) {
                int col = j * 8 + q * 2;
                float2 w;
                w.x = (vals[j * 2 + 0] - mu) * rstd * ln_g[col] + ln_b[col];
                w.y = (vals[j * 2 + 1] - mu) * rstd * ln_g[col + 1] + ln_b[col + 1];
                *(float2*)(o + col) = w;
            }
        }
    }
}

// ---------------- final thin GEMM [16,768000] x [768000,10] -------------------
__global__ void __launch_bounds__(256) k_final1(const float* __restrict__ lin_w) {
    int chunk = blockIdx.x;
    int j0 = chunk * CHUNK_J;
    int tid = threadIdx.x;
    int bg = tid >> 6;
    int kl = tid & 63;
    float acc[4][10];
    #pragma unroll
    for (int bi = 0; bi < 4; bi++)
        #pragma unroll
        for (int c = 0; c < 10; c++) acc[bi][c] = 0.0f;

    for (int k = j0 + kl; k < j0 + CHUNK_J; k += 64) {
        float w[10];
        #pragma unroll
        for (int c = 0; c < 10; c++) w[c] = lin_w[(size_t)c * JTOT + k];
        #pragma unroll
        for (int bi = 0; bi < 4; bi++) {
            float h = g_h[(size_t)(bg * 4 + bi) * JTOT + k];
            #pragma unroll
            for (int c = 0; c < 10; c++) acc[bi][c] += h * w[c];
        }
    }
    __shared__ float red[256 * 40];
    #pragma unroll
    for (int bi = 0; bi < 4; bi++)
        #pragma unroll
        for (int c = 0; c < 10; c++) red[tid * 40 + bi * 10 + c] = acc[bi][c];
    __syncthreads();
    if (tid < 160) {
        int b = tid / 10, c = tid % 10;
        int bg2 = b >> 2, bi2 = b & 3;
        float sum = 0.0f;
        for (int l = 0; l < 64; l++)
            sum += red[(bg2 * 64 + l) * 40 + bi2 * 10 + c];
        g_partial[(chunk * BBATCH + b) * CC + c] = sum;
    }
}

__global__ void k_final2(const float* __restrict__ lin_b, float* __restrict__ out) {
    int i = threadIdx.x;
    if (i < BBATCH * CC) {
        int b = i / CC, c = i % CC;
        float s = lin_b[c];
        for (int ch = 0; ch < FCHUNKS; ch++)
            s += g_partial[(ch * BBATCH + b) * CC + c];
        out[b * CC + c] = s;
    }
}

// ---------------- launch ------------------------------------------------------
extern "C" void kernel_launch(void* const* d_in, const int* in_sizes, int n_in,
                              void* d_out, int out_size) {
    const float* x   = (const float*)d_in[0];
    const int*   ei  = (const int*)d_in[1];
    const float* Wz  = (const float*)d_in[2];
    const float* bz  = (const float*)d_in[3];
    // d_in[4]=W_r, d_in[5]=b_r provably unused (h0 == 0)
    const float* Wh  = (const float*)d_in[6];
    const float* bh  = (const float*)d_in[7];
    const float* lng = (const float*)d_in[8];
    const float* lnb = (const float*)d_in[9];
    const float* lw  = (const float*)d_in[10];
    const float* lb  = (const float*)d_in[11];
    float* out = (float*)d_out;

    cudaFuncSetAttribute(a_prop, cudaFuncAttributeMaxDynamicSharedMemorySize, PROP_SMEM);
    cudaFuncSetAttribute(k_build, cudaFuncAttributeMaxDynamicSharedMemorySize, EE * 8);
    cudaFuncSetAttribute(k_gemm_mma, cudaFuncAttributeMaxDynamicSharedMemorySize, SM_TOTAL_GEMM);

    k_packW<<<(9 * 8192 + 255) / 256, 256>>>(Wz, bz, Wh, bh);   // launch 1
    k_pre<<<1, 1024>>>(ei);                                      // launch 2
    k_build<<<(NN + 7) / 8, 256, EE * 8>>>(ei);                  // launch 3

    for (int lvl = 1; lvl <= 4; lvl++)                           // launches 4-7
        a_prop<<<dim3(SS, 2, 2), 1024, PROP_SMEM>>>(x, lvl);

    k_gemm_mma<<<dim3(SS * 8), 256, SM_TOTAL_GEMM>>>(x, lng, lnb);
    k_final1<<<FCHUNKS, 256>>>(lw);
    k_final2<<<1, 192>>>(lb, out);
}

// round 13
// speedup vs baseline: 2.1949x; 1.1228x over previous
#include <cuda_runtime.h>
#include <cuda_bf16.h>
#include <math.h>
#include <stdint.h>

#define NN 1000
#define FF 64
#define SS 192          // B*T snapshots
#define EE 16000
#define CC 10
#define BBATCH 16
#define JTOT 768000     // T*N*F
#define LN_EPS 1e-5f
#define FCHUNKS 192
#define CHUNK_J 4000

// ---------------- scratch (static device globals; no allocation) -------------
__device__ float g_basis[8][SS * NN * FF];
__device__ float g_h[SS * NN * FF];
__device__ __nv_bfloat16 g_Bpack[2][9][8192];   // [hi/lo][slot][swizzled 128n x 64k]
__device__ float g_bcat[128];
__device__ int   g_offA[NN + 8], g_offB[NN + 8];   // padded for 16B cp.async reads
__device__ uint16_t g_adjA16[EE + 8];            // prop_out srcs (grouped by dst)
__device__ uint16_t g_adjB16[EE + 8];            // prop_in  srcs (grouped by row)
__device__ float g_invdeg_out[NN];
__device__ float g_inv_deg_in[NN];
__device__ float g_partial[FCHUNKS * BBATCH * CC];

// ---------------- helpers -----------------------------------------------------
__device__ __forceinline__ uint32_t smem_u32(const void* p) {
    uint32_t a;
    asm("{ .reg .u64 t; cvta.to.shared.u64 t, %1; cvt.u32.u64 %0, t; }" : "=r"(a) : "l"(p));
    return a;
}
#define SWZ128(o) ((o) ^ (((o) >> 3) & 0x70))

__device__ __forceinline__ void cpa16(uint32_t dst, const void* src) {
    asm volatile("cp.async.cg.shared.global [%0], [%1], 16;" :: "r"(dst), "l"(src));
}
__device__ __forceinline__ void cpa_commit_wait() {
    asm volatile("cp.async.commit_group;" ::: "memory");
    asm volatile("cp.async.wait_group 0;" ::: "memory");
}

__device__ __forceinline__ void ldsm4(uint32_t* r, uint32_t addr) {
    asm volatile("ldmatrix.sync.aligned.m8n8.x4.shared.b16 {%0,%1,%2,%3}, [%4];"
        : "=r"(r[0]), "=r"(r[1]), "=r"(r[2]), "=r"(r[3]) : "r"(addr));
}

__device__ __forceinline__ void mma_bf16(float* d, const uint32_t* a, const uint32_t* b) {
    asm volatile(
        "mma.sync.aligned.m16n8k16.row.col.f32.bf16.bf16.f32 "
        "{%0,%1,%2,%3}, {%4,%5,%6,%7}, {%8,%9}, {%0,%1,%2,%3};"
        : "+f"(d[0]), "+f"(d[1]), "+f"(d[2]), "+f"(d[3])
        : "r"(a[0]), "r"(a[1]), "r"(a[2]), "r"(a[3]), "r"(b[0]), "r"(b[1]));
}

// ---------------- fused graph preprocessing (zero+count+scan, 1 block) --------
__global__ void k_pre(const int* __restrict__ ei) {
    __shared__ int sdo[NN], sdi[NN];
    __shared__ int sA[1024], sB[1024];
    int i = threadIdx.x;
    if (i < NN) { sdo[i] = 0; sdi[i] = 0; }
    __syncthreads();
    for (int e = i; e < EE; e += 1024) {
        atomicAdd(&sdo[ei[e]], 1);
        atomicAdd(&sdi[ei[EE + e]], 1);
    }
    __syncthreads();
    int da = (i < NN) ? sdi[i] : 0;
    int db = (i < NN) ? sdo[i] : 0;
    sA[i] = da; sB[i] = db;
    __syncthreads();
    for (int off = 1; off < 1024; off <<= 1) {
        int va = (i >= off) ? sA[i - off] : 0;
        int vb = (i >= off) ? sB[i - off] : 0;
        __syncthreads();
        sA[i] += va; sB[i] += vb;
        __syncthreads();
    }
    if (i < NN) {
        g_offA[i] = sA[i] - da;
        g_offB[i] = sB[i] - db;
        g_inv_deg_in[i] = 1.0f / (float)da;
        g_invdeg_out[i] = 1.0f / (float)sdo[i];
    }
    if (i == 0) { g_offA[NN] = sA[1023]; g_offB[NN] = sB[1023]; }
}

// deterministic CSR build: stage all edges in smem, one warp per node, ballot compaction
__global__ void k_build(const int* __restrict__ ei) {
    extern __shared__ int2 se[];                   // 16000 x 8B = 128KB
    int tid = threadIdx.x;
    for (int i = tid; i < EE; i += blockDim.x)
        se[i] = make_int2(ei[i], ei[EE + i]);
    __syncthreads();
    int warp = blockIdx.x * (blockDim.x >> 5) + (tid >> 5);
    int lane = tid & 31;
    if (warp >= NN) return;
    int n = warp;
    int pa = g_offA[n], pb = g_offB[n];
    for (int e0 = 0; e0 < EE; e0 += 32) {
        int2 rc = se[e0 + lane];
        unsigned mA = __ballot_sync(0xffffffffu, rc.y == n);
        unsigned mB = __ballot_sync(0xffffffffu, rc.x == n);
        if (rc.y == n) {
            int pos = pa + __popc(mA & ((1u << lane) - 1));
            g_adjA16[pos] = (uint16_t)rc.x;
        }
        if (rc.x == n) {
            int pos = pb + __popc(mB & ((1u << lane) - 1));
            g_adjB16[pos] = (uint16_t)rc.y;
        }
        pa += __popc(mA); pb += __popc(mB);
    }
}

// pack weights into bf16 hi/lo images (SW128-swizzled, [n][k] rows of 128B)
__global__ void k_packW(const float* __restrict__ Wz, const float* __restrict__ bz,
                        const float* __restrict__ Wh, const float* __restrict__ bh) {
    int i = blockIdx.x * blockDim.x + threadIdx.x;
    if (i < 128) g_bcat[i] = (i < 64) ? bz[i] : bh[i - 64];
    if (i >= 9 * 8192) return;
    int slot = i >> 13;
    int r = i & 8191;
    int n = r >> 6, k = r & 63;
    const float* W = (n < 64) ? Wz : Wh;
    int f = n & 63;
    float v;
    if (slot == 0) {
        v = W[(0 * 5 + 0) * 128 * 64 + k * 64 + f]
          + W[(1 * 5 + 0) * 128 * 64 + k * 64 + f];
    } else {
        int kc = (slot + 1) >> 1;
        int dir = (slot - 1) & 1;
        v = W[(dir * 5 + kc) * 128 * 64 + k * 64 + f];
    }
    __nv_bfloat16 hi = __float2bfloat16(v);
    __nv_bfloat16 lo = __float2bfloat16(v - __bfloat162float(hi));
    uint32_t off = SWZ128((uint32_t)(n * 128 + k * 2));
    g_Bpack[0][slot][off >> 1] = hi;
    g_Bpack[1][slot][off >> 1] = lo;
}

// ---------------- Chebyshev propagation (all-smem, paired-edge float2) --------
// dir0 plane pre-scaled by 1/deg_out[node]; half-warp 0 -> edge j, half-warp 1
// -> edge j+1, each lane covers 2 features via LDS.64; shfl merge at the end.
#define ADJ_OFF  128000     // 16000 uint16
#define OFF_OFF  160000     // 1008 ints
#define INV_OFF  164032     // 1000 floats
#define PROP_SMEM 168032

__global__ void __launch_bounds__(1024, 1) a_prop(const float* __restrict__ x, int level) {
    extern __shared__ float sv[];
    float2* sv2 = (float2*)sv;                      // [1000][16]
    uint16_t* sadj = (uint16_t*)((char*)sv + ADJ_OFF);
    int* soff = (int*)((char*)sv + OFF_OFF);
    float* sinv = (float*)((char*)sv + INV_OFF);
    int s = blockIdx.x, dir = blockIdx.y, half = blockIdx.z;
    int dst_slot = 2 * level - 1 + dir;
    const float* src;
    const float* prev = nullptr;
    if (level == 1) {
        src = x + (size_t)s * NN * FF;
    } else {
        int ssrc = 2 * (level - 1) - 1 + dir;
        src = g_basis[ssrc - 1] + (size_t)s * NN * FF;
        if (level == 2) prev = x + (size_t)s * NN * FF;
        else prev = g_basis[(2 * (level - 2) - 1) - 1] + (size_t)s * NN * FF;
    }
    uint32_t sb = smem_u32(sv);
    int tid = threadIdx.x;
    #pragma unroll
    for (int it = 0; it < 8; it++) {
        int i = tid + it * 1024;
        if (i < 8000) {
            int n = i >> 3, q = i & 7;
            cpa16(sb + (uint32_t)(n * 128 + q * 16),
                  src + (size_t)n * FF + half * 32 + q * 4);
        }
    }
    {
        const uint16_t* adj = dir ? g_adjB16 : g_adjA16;
        #pragma unroll
        for (int it = 0; it < 2; it++) {
            int i = tid + it * 1024;
            if (i < 2000)
                cpa16(sb + ADJ_OFF + i * 16, adj + i * 8);
        }
    }
    if (tid < 251) {
        const int* offsrc = dir ? g_offB : g_offA;
        cpa16(sb + OFF_OFF + tid * 16, offsrc + tid * 4);
    }
    if (tid >= 512 && tid < 762) {
        const float* invsrc = dir ? g_inv_deg_in : g_invdeg_out;
        int i = tid - 512;
        cpa16(sb + INV_OFF + i * 16, invsrc + i * 4);
    }
    cpa_commit_wait();
    __syncthreads();

    if (dir == 0) {     // pre-scale values by 1/deg_out[node]
        #pragma unroll
        for (int it = 0; it < 32; it++) {
            int i = tid + it * 1024;
            if (i < 32000) sv[i] *= sinv[i >> 5];
        }
        __syncthreads();
    }

    int lane = tid & 31;
    int w = tid >> 5;                     // 32 warps
    int el = lane >> 4, fp = lane & 15;   // edge-slot 0/1, feature-pair 0..15
    float* out = g_basis[dst_slot - 1] + (size_t)s * NN * FF;

    for (int n = w; n < NN; n += 32) {
        int b = soff[n], e = soff[n + 1];
        float ax0 = 0.f, ay0 = 0.f, ax1 = 0.f, ay1 = 0.f;
        int j = b + el;
        for (; j + 2 < e; j += 4) {
            int s0 = sadj[j];
            int s1 = sadj[j + 2];
            float2 v0 = sv2[s0 * 16 + fp];
            float2 v1 = sv2[s1 * 16 + fp];
            ax0 += v0.x; ay0 += v0.y;
            ax1 += v1.x; ay1 += v1.y;
        }
        if (j < e) {
            int s0 = sadj[j];
            float2 v0 = sv2[s0 * 16 + fp];
            ax0 += v0.x; ay0 += v0.y;
        }
        float ax = ax0 + ax1, ay = ay0 + ay1;
        ax += __shfl_xor_sync(0xffffffffu, ax, 16);
        ay += __shfl_xor_sync(0xffffffffu, ay, 16);
        if (dir == 1) { float iv = sinv[n]; ax *= iv; ay *= iv; }
        if (el == 0) {
            int f = half * 32 + fp * 2;
            float2 r;
            if (level == 1) { r.x = ax; r.y = ay; }
            else {
                float2 pv = *(const float2*)(prev + n * FF + f);
                r.x = 2.0f * ax - pv.x;
                r.y = 2.0f * ay - pv.y;
            }
            *(float2*)(out + n * FF + f) = r;
        }
    }
}

// ---------------- mma.sync bf16 GEMM: 128-thr blocks, 2 CTAs/SM ---------------
// A prefetched into registers (LDG, hidden behind mma), converted reg->smem.
// B double-buffered via cp.async. 3-pass bf16 split, fp32 accum, fused epilogue.
#define SM_AHI 0            // 8192
#define SM_ALO 8192         // 8192
#define SM_B   16384        // 2 x 32768 (hi at +0, lo at +16384)
#define SM_TOTAL_GEMM 81920

__global__ void __launch_bounds__(128, 2) k_gemm_mma(const float* __restrict__ x,
                                                     const float* __restrict__ ln_g,
                                                     const float* __restrict__ ln_b) {
    extern __shared__ char smem[];
    uint32_t sb = smem_u32(smem);
    const int tid = threadIdx.x;
    const int wid = tid >> 5, lane = tid & 31;
    const int s = blockIdx.x >> 4;
    const int row0 = (blockIdx.x & 15) << 6;    // 64-row tile
    const int m0 = wid << 4;                    // warp rows within tile

    float acc[16][4];
    #pragma unroll
    for (int t = 0; t < 16; t++)
        #pragma unroll
        for (int c = 0; c < 4; c++) acc[t][c] = 0.0f;

    const uint32_t a_rowoff = (uint32_t)((m0 + (lane & 15)) * 128 + ((lane >> 4) * 16));
    const uint32_t b_rowoff = (uint32_t)((((lane >> 4) * 8 + (lane & 7)) * 128) + (((lane >> 3) & 1) * 16));

    float4 pf[8];
    auto ldA = [&](int slot) {
        const float* plane = (slot == 0) ? (x + (size_t)s * NN * FF)
                                         : (g_basis[slot - 1] + (size_t)s * NN * FF);
        #pragma unroll
        for (int i = 0; i < 8; i++) {
            int j = tid + i * 128;               // 1024 chunks: 64 rows x 16 quads
            int node = row0 + (j >> 4);
            pf[i] = (node < NN) ? *(const float4*)(plane + (size_t)node * FF + (j & 15) * 4)
                                : make_float4(0.f, 0.f, 0.f, 0.f);
        }
    };
    auto issueB = [&](int slot, int buf) {
        const char* bh = (const char*)&g_Bpack[0][slot][0];
        const char* bl = (const char*)&g_Bpack[1][slot][0];
        #pragma unroll
        for (int i = 0; i < 8; i++) {
            int j = tid + i * 128;               // 1024 chunks each image
            cpa16(sb + SM_B + buf * 32768 + j * 16, bh + j * 16);
            cpa16(sb + SM_B + buf * 32768 + 16384 + j * 16, bl + j * 16);
        }
        asm volatile("cp.async.commit_group;" ::: "memory");
    };

    ldA(0);
    issueB(0, 0);
    for (int slot = 0; slot < 9; slot++) {
        int buf = slot & 1;
        __syncthreads();                         // AHI/ALO free of prev-slot readers
        #pragma unroll
        for (int i = 0; i < 8; i++) {
            int j = tid + i * 128;
            int m = j >> 4, kq = j & 15;
            float4 v = pf[i];
            __nv_bfloat16 h0 = __float2bfloat16(v.x);
            __nv_bfloat16 h1 = __float2bfloat16(v.y);
            __nv_bfloat16 h2 = __float2bfloat16(v.z);
            __nv_bfloat16 h3 = __float2bfloat16(v.w);
            __nv_bfloat16 l0 = __float2bfloat16(v.x - __bfloat162float(h0));
            __nv_bfloat16 l1 = __float2bfloat16(v.y - __bfloat162float(h1));
            __nv_bfloat16 l2 = __float2bfloat16(v.z - __bfloat162float(h2));
            __nv_bfloat16 l3 = __float2bfloat16(v.w - __bfloat162float(h3));
            uint32_t off = SWZ128((uint32_t)(m * 128 + kq * 8));
            *(__nv_bfloat162*)(smem + SM_AHI + off)     = __halves2bfloat162(h0, h1);
            *(__nv_bfloat162*)(smem + SM_AHI + off + 4) = __halves2bfloat162(h2, h3);
            *(__nv_bfloat162*)(smem + SM_ALO + off)     = __halves2bfloat162(l0, l1);
            *(__nv_bfloat162*)(smem + SM_ALO + off + 4) = __halves2bfloat162(l2, l3);
        }
        if (slot < 8) {
            ldA(slot + 1);                       // LDG prefetch; consumed next iter
            issueB(slot + 1, buf ^ 1);
            asm volatile("cp.async.wait_group 1;" ::: "memory");
        } else {
            asm volatile("cp.async.wait_group 0;" ::: "memory");
        }
        __syncthreads();

        uint32_t bBH = sb + SM_B + buf * 32768;
        uint32_t bBL = bBH + 16384;
        #pragma unroll
        for (int kk = 0; kk < 4; kk++) {
            const uint32_t kbase = kk * 32;
            uint32_t aAh[4], aAl[4];
            ldsm4(aAh, sb + SM_AHI + SWZ128(a_rowoff + kbase));
            ldsm4(aAl, sb + SM_ALO + SWZ128(a_rowoff + kbase));
            uint32_t bF[8][4];
            #pragma unroll
            for (int p = 0; p < 8; p++)
                ldsm4(bF[p], bBH + SWZ128(b_rowoff + p * 2048 + kbase));
            #pragma unroll
            for (int t = 0; t < 16; t++) {
                const uint32_t* bf = &bF[t >> 1][(t & 1) * 2];
                mma_bf16(acc[t], aAh, bf);     // Ahi * Bhi
                mma_bf16(acc[t], aAl, bf);     // Alo * Bhi
            }
            #pragma unroll
            for (int p = 0; p < 8; p++)
                ldsm4(bF[p], bBL + SWZ128(b_rowoff + p * 2048 + kbase));
            #pragma unroll
            for (int t = 0; t < 16; t++)
                mma_bf16(acc[t], aAh, &bF[t >> 1][(t & 1) * 2]);   // Ahi * Blo
        }
    }

    // fused epilogue: gates + relu + LayerNorm (register/shfl local, __expf)
    int q = lane & 3, rl = lane >> 2;
    #pragma unroll
    for (int h = 0; h < 2; h++) {
        float s1 = 0.f, s2 = 0.f;
        float vals[16];
        #pragma unroll
        for (int j = 0; j < 8; j++) {
            #pragma unroll
            for (int p = 0; p < 2; p++) {
                int col = j * 8 + q * 2 + p;
                float zc = acc[j][h * 2 + p] + g_bcat[col];
                float tc = acc[8 + j][h * 2 + p] + g_bcat[64 + col];
                float z = 1.0f / (1.0f + __expf(-zc));
                float tt = 1.0f - 2.0f / (__expf(2.0f * tc) + 1.0f);
                float v = fmaxf((1.0f - z) * tt, 0.0f);
                vals[j * 2 + p] = v; s1 += v; s2 += v * v;
            }
        }
        s1 += __shfl_xor_sync(0xffffffffu, s1, 1);
        s1 += __shfl_xor_sync(0xffffffffu, s1, 2);
        s2 += __shfl_xor_sync(0xffffffffu, s2, 1);
        s2 += __shfl_xor_sync(0xffffffffu, s2, 2);
        float mu = s1 * (1.0f / 64.0f);
        float var = s2 * (1.0f / 64.0f) - mu * mu;
        float rstd = rsqrtf(var + LN_EPS);
        int node = row0 + m0 + rl + h * 8;
        if (node < NN) {
            float* o = g_h + ((size_t)s * NN + node) * FF;
            #pragma unroll
            for (int j = 0; j < 8; j++) {
                int col = j * 8 + q * 2;
                float2 w;
                w.x = (vals[j * 2 + 0] - mu) * rstd * ln_g[col] + ln_b[col];
                w.y = (vals[j * 2 + 1] - mu) * rstd * ln_g[col + 1] + ln_b[col + 1];
                *(float2*)(o + col) = w;
            }
        }
    }
}

// ---------------- final thin GEMM [16,768000] x [768000,10] -------------------
__global__ void __launch_bounds__(256) k_final1(const float* __restrict__ lin_w) {
    int chunk = blockIdx.x;
    int j0 = chunk * CHUNK_J;
    int tid = threadIdx.x;
    int bg = tid >> 6;
    int kl = tid & 63;
    float acc[4][10];
    #pragma unroll
    for (int bi = 0; bi < 4; bi++)
        #pragma unroll
        for (int c = 0; c < 10; c++) acc[bi][c] = 0.0f;

    for (int k = j0 + kl; k < j0 + CHUNK_J; k += 64) {
        float w[10];
        #pragma unroll
        for (int c = 0; c < 10; c++) w[c] = lin_w[(size_t)c * JTOT + k];
        #pragma unroll
        for (int bi = 0; bi < 4; bi++) {
            float h = g_h[(size_t)(bg * 4 + bi) * JTOT + k];
            #pragma unroll
            for (int c = 0; c < 10; c++) acc[bi][c] += h * w[c];
        }
    }
    __shared__ float red[256 * 40];
    #pragma unroll
    for (int bi = 0; bi < 4; bi++)
        #pragma unroll
        for (int c = 0; c < 10; c++) red[tid * 40 + bi * 10 + c] = acc[bi][c];
    __syncthreads();
    if (tid < 160) {
        int b = tid / 10, c = tid % 10;
        int bg2 = b >> 2, bi2 = b & 3;
        float sum = 0.0f;
        for (int l = 0; l < 64; l++)
            sum += red[(bg2 * 64 + l) * 40 + bi2 * 10 + c];
        g_partial[(chunk * BBATCH + b) * CC + c] = sum;
    }
}

__global__ void k_final2(const float* __restrict__ lin_b, float* __restrict__ out) {
    int i = threadIdx.x;
    if (i < BBATCH * CC) {
        int b = i / CC, c = i % CC;
        float s = lin_b[c];
        for (int ch = 0; ch < FCHUNKS; ch++)
            s += g_partial[(ch * BBATCH + b) * CC + c];
        out[b * CC + c] = s;
    }
}

// ---------------- launch ------------------------------------------------------
extern "C" void kernel_launch(void* const* d_in, const int* in_sizes, int n_in,
                              void* d_out, int out_size) {
    const float* x   = (const float*)d_in[0];
    const int*   ei  = (const int*)d_in[1];
    const float* Wz  = (const float*)d_in[2];
    const float* bz  = (const float*)d_in[3];
    // d_in[4]=W_r, d_in[5]=b_r provably unused (h0 == 0)
    const float* Wh  = (const float*)d_in[6];
    const float* bh  = (const float*)d_in[7];
    const float* lng = (const float*)d_in[8];
    const float* lnb = (const float*)d_in[9];
    const float* lw  = (const float*)d_in[10];
    const float* lb  = (const float*)d_in[11];
    float* out = (float*)d_out;

    cudaFuncSetAttribute(a_prop, cudaFuncAttributeMaxDynamicSharedMemorySize, PROP_SMEM);
    cudaFuncSetAttribute(k_build, cudaFuncAttributeMaxDynamicSharedMemorySize, EE * 8);
    cudaFuncSetAttribute(k_gemm_mma, cudaFuncAttributeMaxDynamicSharedMemorySize, SM_TOTAL_GEMM);

    k_packW<<<(9 * 8192 + 255) / 256, 256>>>(Wz, bz, Wh, bh);   // launch 1
    k_pre<<<1, 1024>>>(ei);                                      // launch 2
    k_build<<<(NN + 7) / 8, 256, EE * 8>>>(ei);                  // launch 3

    for (int lvl = 1; lvl <= 4; lvl++)                           // launches 4-7
        a_prop<<<dim3(SS, 2, 2), 1024, PROP_SMEM>>>(x, lvl);

    k_gemm_mma<<<dim3(SS * 16), 128, SM_TOTAL_GEMM>>>(x, lng, lnb);
    k_final1<<<FCHUNKS, 256>>>(lw);
    k_final2<<<1, 192>>>(lb, out);
}